// round 6
// baseline (speedup 1.0000x reference)
#include <cuda_runtime.h>
#include <cuda_bf16.h>
#include <cstdio>

// Problem constants
#define N_   100000
#define S_   2
#define G_   8
#define E_   400000
#define MID_ 256
#define L_   4
#define INC  265
#define INP  272          // padded input channels (multiple of 16)
#define M_   (N_ * S_)    // 200000 rows

// ---------------- scratch (device globals; no allocation allowed) ----------
__device__ float g_X0[(size_t)M_ * 256];
__device__ float g_X1[(size_t)M_ * 256];
__device__ float g_YF[(size_t)M_ * 128];
__device__ float g_YR[(size_t)M_ * 128];
__device__ float g_AF[(size_t)M_ * 128];
__device__ float g_AR[(size_t)M_ * 128];
__device__ float g_F [(size_t)M_ * INP];
__device__ float g_WCAT[(size_t)L_ * 256 * 512];
__device__ float g_PW[(size_t)INP * 256];
__device__ float g_degF[N_];
__device__ float g_degR[N_];
__device__ float g_pooled[S_ * G_];

// ---------------- helpers ---------------------------------------------------
__device__ __forceinline__ void red4(float4* addr, float4 v) {
    asm volatile("red.global.add.v4.f32 [%0], {%1,%2,%3,%4};"
                 :: "l"(addr), "f"(v.x), "f"(v.y), "f"(v.z), "f"(v.w)
                 : "memory");
}

// ---------------- prep: concat weights + pad preW ---------------------------
__global__ void wcat_kernel(const float* __restrict__ cWl, const float* __restrict__ cWr,
                            const float* __restrict__ rWl, const float* __restrict__ rWr,
                            float* __restrict__ WCAT) {
    int idx = blockIdx.x * blockDim.x + threadIdx.x;
    int total = L_ * 256 * 512;
    if (idx >= total) return;
    int l = idx / (256 * 512);
    int rem = idx - l * (256 * 512);
    int k = rem >> 9;         // /512
    int j = rem & 511;
    float v;
    int base = (l * 256 + k) * 128;
    if (j < 128)      v = cWl[base + j];
    else if (j < 256) v = cWr[base + j - 128];
    else if (j < 384) v = rWl[base + j - 256];
    else              v = rWr[base + j - 384];
    WCAT[idx] = v;
}

__global__ void pw_kernel(const float* __restrict__ preW, float* __restrict__ PW) {
    int idx = blockIdx.x * blockDim.x + threadIdx.x;
    if (idx >= INP * 256) return;
    int k = idx >> 8;   // /256
    int j = idx & 255;
    PW[idx] = (k < INC) ? preW[k * 256 + j] : 0.f;
}

// ---------------- degrees ----------------------------------------------------
__global__ void degree_kernel(const int* __restrict__ src, const int* __restrict__ tgt,
                              float* degF, float* degR) {
    int e = blockIdx.x * blockDim.x + threadIdx.x;
    if (e >= E_) return;
    atomicAdd(&degF[tgt[e]], 1.f);
    atomicAdd(&degR[src[e]], 1.f);
}

__global__ void inv_kernel(float* degF, float* degR) {
    int n = blockIdx.x * blockDim.x + threadIdx.x;
    if (n >= N_) return;
    degF[n] = 1.f / fmaxf(degF[n], 1.f);
    degR[n] = 1.f / fmaxf(degR[n], 1.f);
}

// ---------------- feature construction --------------------------------------
__global__ void feat_kernel(const float* __restrict__ x_feat, const float* __restrict__ dim_feat,
                            const float* __restrict__ layout_feat, const float* __restrict__ tile_feat,
                            const float* __restrict__ opcode_embed,
                            const int* __restrict__ node_opcode, const int* __restrict__ batch,
                            float* __restrict__ F) {
    int idx = blockIdx.x * blockDim.x + threadIdx.x;
    const int total = M_ * INP;
    if (idx >= total) return;
    int c = idx % INP;
    int m = idx / INP;
    int s = m & 1;
    int n = m >> 1;
    float v;
    if (c < 53)       v = x_feat[n * 53 + c];
    else if (c < 85)  v = opcode_embed[node_opcode[n] * 32 + (c - 53)];
    else if (c < 223) v = dim_feat[n * 138 + (c - 85)];
    else if (c < 247) v = layout_feat[n * (S_ * 24) + s * 24 + (c - 223)];
    else if (c < 265) v = tile_feat[batch[n] * (S_ * 18) + s * 18 + (c - 247)];
    else              v = 0.f;
    F[idx] = v;
}

// ---------------- SGEMM: [M,K] @ [K,ldb-tile] -------------------------------
// BM=128, BN=128, BK=16, 256 threads, 8x8 per thread.
// mode 0 (pre): out = relu(acc + preb[col]) -> O0 (row stride 256)
// mode 1 (layer): by=0 -> YF(O0, stride128), by=1 -> Xnext(O2) cols 0:128,
//                 by=2 -> YR(O1, stride128), by=3 -> Xnext(O2) cols 128:256
#define BM 128
#define BN 128
#define BK 16

__global__ void __launch_bounds__(256, 2)
sgemm_k(const float* __restrict__ A, const float* __restrict__ B,
        int M, int K, int ldb, int mode,
        const float* __restrict__ preb,
        float* __restrict__ O0, float* __restrict__ O1, float* __restrict__ O2) {
    __shared__ float As[BK][BM];
    __shared__ float Bs[BK][BN];
    const int tid = threadIdx.x;
    const int bm = blockIdx.x * BM;
    const int bn = blockIdx.y * BN;
    const int tx = tid & 15, ty = tid >> 4;

    float acc[8][8];
#pragma unroll
    for (int i = 0; i < 8; i++)
#pragma unroll
        for (int j = 0; j < 8; j++) acc[i][j] = 0.f;

    for (int k0 = 0; k0 < K; k0 += BK) {
        // load A tile (transposed into smem)
#pragma unroll
        for (int t = 0; t < 2; t++) {
            int i = tid + t * 256;
            int r = i >> 2;
            int c = (i & 3) * 4;
            float4 v = make_float4(0.f, 0.f, 0.f, 0.f);
            int row = bm + r;
            if (row < M) v = *(const float4*)(A + (size_t)row * K + k0 + c);
            As[c + 0][r] = v.x; As[c + 1][r] = v.y;
            As[c + 2][r] = v.z; As[c + 3][r] = v.w;
        }
        // load B tile
#pragma unroll
        for (int t = 0; t < 2; t++) {
            int i = tid + t * 256;
            int kk = i >> 5;
            int c = (i & 31) * 4;
            float4 v = *(const float4*)(B + (size_t)(k0 + kk) * ldb + bn + c);
            *(float4*)&Bs[kk][c] = v;
        }
        __syncthreads();
#pragma unroll
        for (int kk = 0; kk < BK; kk++) {
            float4 a0 = *(float4*)&As[kk][ty * 8];
            float4 a1 = *(float4*)&As[kk][ty * 8 + 4];
            float4 b0 = *(float4*)&Bs[kk][tx * 8];
            float4 b1 = *(float4*)&Bs[kk][tx * 8 + 4];
            float a[8] = {a0.x, a0.y, a0.z, a0.w, a1.x, a1.y, a1.z, a1.w};
            float b[8] = {b0.x, b0.y, b0.z, b0.w, b1.x, b1.y, b1.z, b1.w};
#pragma unroll
            for (int i = 0; i < 8; i++)
#pragma unroll
                for (int j = 0; j < 8; j++) acc[i][j] += a[i] * b[j];
        }
        __syncthreads();
    }

    const int colLocal = tx * 8;                 // 0..120 within 128-col group
    if (mode == 0) {
        const int col = bn + colLocal;
#pragma unroll
        for (int i = 0; i < 8; i++) {
            int row = bm + ty * 8 + i;
            if (row >= M) continue;
            float4 v0, v1;
            v0.x = fmaxf(acc[i][0] + preb[col + 0], 0.f);
            v0.y = fmaxf(acc[i][1] + preb[col + 1], 0.f);
            v0.z = fmaxf(acc[i][2] + preb[col + 2], 0.f);
            v0.w = fmaxf(acc[i][3] + preb[col + 3], 0.f);
            v1.x = fmaxf(acc[i][4] + preb[col + 4], 0.f);
            v1.y = fmaxf(acc[i][5] + preb[col + 5], 0.f);
            v1.z = fmaxf(acc[i][6] + preb[col + 6], 0.f);
            v1.w = fmaxf(acc[i][7] + preb[col + 7], 0.f);
            float* p = O0 + (size_t)row * 256 + col;
            *(float4*)p = v0;
            *(float4*)(p + 4) = v1;
        }
    } else {
        const int by = blockIdx.y;
#pragma unroll
        for (int i = 0; i < 8; i++) {
            int row = bm + ty * 8 + i;
            if (row >= M) continue;
            float4 v0 = make_float4(acc[i][0], acc[i][1], acc[i][2], acc[i][3]);
            float4 v1 = make_float4(acc[i][4], acc[i][5], acc[i][6], acc[i][7]);
            float* p;
            if (by == 0)      p = O0 + (size_t)row * 128 + colLocal;
            else if (by == 1) p = O2 + (size_t)row * 256 + colLocal;
            else if (by == 2) p = O1 + (size_t)row * 128 + colLocal;
            else              p = O2 + (size_t)row * 256 + 128 + colLocal;
            *(float4*)p = v0;
            *(float4*)(p + 4) = v1;
        }
    }
}

// ---------------- edge scatter (both directions) ----------------------------
// Per node, Y*/A* hold S_*128 = 256 floats = 64 float4.
__global__ void scatter_kernel(const float4* __restrict__ YF, const float4* __restrict__ YR,
                               float4* __restrict__ AF, float4* __restrict__ AR,
                               const int* __restrict__ src, const int* __restrict__ tgt) {
    long idx = (long)blockIdx.x * blockDim.x + threadIdx.x;
    const long total = (long)E_ * 64;
    if (idx >= total) return;
    int e = (int)(idx >> 6);
    int c = (int)(idx & 63);
    int s = __ldg(src + e);
    int t = __ldg(tgt + e);
    float4 v = __ldg(&YF[(size_t)s * 64 + c]);
    red4(AF + (size_t)t * 64 + c, v);
    float4 w = __ldg(&YR[(size_t)t * 64 + c]);
    red4(AR + (size_t)s * 64 + c, w);
}

// ---------------- combine + relu + (pool for last 2 layers) ----------------
__global__ void combine_kernel(float* __restrict__ X, const float* __restrict__ AF,
                               const float* __restrict__ AR,
                               const float* __restrict__ invF, const float* __restrict__ invR,
                               const float* __restrict__ cb, const float* __restrict__ rb,
                               const float* __restrict__ headW, const int* __restrict__ batch,
                               float* __restrict__ pooled, int layer) {
    int warp = (blockIdx.x * blockDim.x + threadIdx.x) >> 5;
    int lane = threadIdx.x & 31;
    if (warp >= M_) return;
    int m = warp;
    int n = m >> 1;
    int s = m & 1;
    const float iF = invF[n];
    const float iR = invR[n];
    float4* Xr = (float4*)(X + (size_t)m * 256);
    const float4* aF = (const float4*)(AF + (size_t)m * 128);
    const float4* aR = (const float4*)(AR + (size_t)m * 128);
    const int doPool = (layer >= L_ - 2);
    const int hoff = (layer - (L_ - 2)) * 256;
    float dot = 0.f;
#pragma unroll
    for (int u = 0; u < 2; u++) {
        int j4 = lane * 2 + u;            // float4 index 0..63 within row
        float4 xv = Xr[j4];
        float4 av, bv;
        float sc;
        if (j4 < 32) {
            av = aF[j4]; sc = iF;
            bv = *(const float4*)(cb + j4 * 4);
        } else {
            av = aR[j4 - 32]; sc = iR;
            bv = *(const float4*)(rb + (j4 - 32) * 4);
        }
        xv.x = fmaxf(xv.x + av.x * sc + bv.x, 0.f);
        xv.y = fmaxf(xv.y + av.y * sc + bv.y, 0.f);
        xv.z = fmaxf(xv.z + av.z * sc + bv.z, 0.f);
        xv.w = fmaxf(xv.w + av.w * sc + bv.w, 0.f);
        Xr[j4] = xv;
        if (doPool) {
            float4 hw = __ldg((const float4*)(headW + hoff) + j4);
            dot += xv.x * hw.x + xv.y * hw.y + xv.z * hw.z + xv.w * hw.w;
        }
    }
    if (doPool) {
#pragma unroll
        for (int o = 16; o; o >>= 1) dot += __shfl_down_sync(0xffffffffu, dot, o);
        if (lane == 0) atomicAdd(&pooled[s * G_ + batch[n]], dot);
    }
}

// ---------------- final ------------------------------------------------------
__global__ void final_kernel(const float* __restrict__ pooled, const float* __restrict__ headb,
                             float* __restrict__ out) {
    int i = threadIdx.x;
    if (i < S_ * G_) {
        int g = i >> 1;   // out is [G, S, 1]
        int s = i & 1;
        out[i] = pooled[s * G_ + g] + headb[0];
    }
}

// ---------------- launch -----------------------------------------------------
extern "C" void kernel_launch(void* const* d_in, const int* in_sizes, int n_in,
                              void* d_out, int out_size) {
    const float* x_feat       = (const float*)d_in[0];
    const float* dim_feat     = (const float*)d_in[1];
    const float* layout_feat  = (const float*)d_in[2];
    const float* tile_feat    = (const float*)d_in[3];
    const float* opcode_embed = (const float*)d_in[4];
    const float* preW         = (const float*)d_in[5];
    const float* preb         = (const float*)d_in[6];
    const float* convWl       = (const float*)d_in[7];
    const float* convWr       = (const float*)d_in[8];
    const float* convb        = (const float*)d_in[9];
    const float* revWl        = (const float*)d_in[10];
    const float* revWr        = (const float*)d_in[11];
    const float* revb         = (const float*)d_in[12];
    const float* headW        = (const float*)d_in[13];
    const float* headb        = (const float*)d_in[14];
    const int*   node_opcode  = (const int*)d_in[15];
    const int*   batch        = (const int*)d_in[16];
    const int*   edge_index   = (const int*)d_in[17];
    const int* src = edge_index;
    const int* tgt = edge_index + E_;

    float *X0, *X1, *YF, *YR, *AF, *AR, *F, *WCAT, *PW, *degF, *degR, *pooled;
    cudaGetSymbolAddress((void**)&X0, g_X0);
    cudaGetSymbolAddress((void**)&X1, g_X1);
    cudaGetSymbolAddress((void**)&YF, g_YF);
    cudaGetSymbolAddress((void**)&YR, g_YR);
    cudaGetSymbolAddress((void**)&AF, g_AF);
    cudaGetSymbolAddress((void**)&AR, g_AR);
    cudaGetSymbolAddress((void**)&F,  g_F);
    cudaGetSymbolAddress((void**)&WCAT, g_WCAT);
    cudaGetSymbolAddress((void**)&PW, g_PW);
    cudaGetSymbolAddress((void**)&degF, g_degF);
    cudaGetSymbolAddress((void**)&degR, g_degR);
    cudaGetSymbolAddress((void**)&pooled, g_pooled);

    // prep
    wcat_kernel<<<(L_ * 256 * 512 + 255) / 256, 256>>>(convWl, convWr, revWl, revWr, WCAT);
    pw_kernel<<<(INP * 256 + 255) / 256, 256>>>(preW, PW);
    cudaMemsetAsync(degF, 0, (size_t)N_ * 4);
    cudaMemsetAsync(degR, 0, (size_t)N_ * 4);
    cudaMemsetAsync(pooled, 0, (size_t)S_ * G_ * 4);
    degree_kernel<<<(E_ + 255) / 256, 256>>>(src, tgt, degF, degR);
    inv_kernel<<<(N_ + 255) / 256, 256>>>(degF, degR);

    // features + pre-layer GEMM
    feat_kernel<<<((size_t)M_ * INP + 255) / 256, 256>>>(
        x_feat, dim_feat, layout_feat, tile_feat, opcode_embed, node_opcode, batch, F);
    dim3 gpre((M_ + BM - 1) / BM, 2);
    sgemm_k<<<gpre, 256>>>(F, PW, M_, INP, 256, 0, preb, X0, nullptr, nullptr);

    float* cur = X0;
    float* nxt = X1;
    for (int l = 0; l < L_; l++) {
        cudaMemsetAsync(AF, 0, (size_t)M_ * 128 * 4);
        cudaMemsetAsync(AR, 0, (size_t)M_ * 128 * 4);
        dim3 gl((M_ + BM - 1) / BM, 4);
        sgemm_k<<<gl, 256>>>(cur, WCAT + (size_t)l * 256 * 512, M_, 256, 512, 1,
                             nullptr, YF, YR, nxt);
        scatter_kernel<<<(int)(((long)E_ * 64 + 255) / 256), 256>>>(
            (const float4*)YF, (const float4*)YR, (float4*)AF, (float4*)AR, src, tgt);
        combine_kernel<<<(M_ * 32 + 255) / 256, 256>>>(
            nxt, AF, AR, degF, degR, convb + l * 128, revb + l * 128,
            headW, batch, pooled, l);
        float* t = cur; cur = nxt; nxt = t;
    }

    final_kernel<<<1, 32>>>(pooled, headb, (float*)d_out);
}

// round 13
// speedup vs baseline: 1.7487x; 1.7487x over previous
#include <cuda_runtime.h>
#include <cuda_fp16.h>
#include <cstdint>

// Problem constants
#define N_   100000
#define S_   2
#define G_   8
#define E_   400000
#define L_   4
#define INC  265
#define KPRE 320          // padded pre-layer K (10 chunks of 32)
#define M_   (N_ * S_)    // 200000 rows

// ---------------- scratch (device globals; no allocation allowed) ----------
__device__ float   g_Y  [(size_t)M_ * 512];     // layer GEMM out (fp32)
__device__ __half  g_Xh0[(size_t)M_ * 256];
__device__ __half  g_Xl0[(size_t)M_ * 256];
__device__ __half  g_Xh1[(size_t)M_ * 256];
__device__ __half  g_Xl1[(size_t)M_ * 256];
__device__ __half  g_Fh [(size_t)M_ * KPRE];
__device__ __half  g_Fl [(size_t)M_ * KPRE];
__device__ float   g_AF [(size_t)M_ * 128];
__device__ float   g_AR [(size_t)M_ * 128];
__device__ __half  g_Wth[(size_t)L_ * 512 * 256];  // W^T hi: [l][out col j][k]
__device__ __half  g_Wtl[(size_t)L_ * 512 * 256];
__device__ __half  g_PWh[(size_t)256 * KPRE];      // preW^T hi [256][320]
__device__ __half  g_PWl[(size_t)256 * KPRE];
__device__ float g_degF[N_];
__device__ float g_degR[N_];
__device__ float g_pooled[S_ * G_];

// ---------------- helpers ----------------------------------------------------
__device__ __forceinline__ uint32_t smem_u32(const void* p) {
    uint32_t a;
    asm("{ .reg .u64 t; cvta.to.shared.u64 t, %1; cvt.u32.u64 %0, t; }" : "=r"(a) : "l"(p));
    return a;
}

__device__ __forceinline__ void red4(float4* addr, float4 v) {
    asm volatile("red.global.add.v4.f32 [%0], {%1,%2,%3,%4};"
                 :: "l"(addr), "f"(v.x), "f"(v.y), "f"(v.z), "f"(v.w) : "memory");
}

__device__ __forceinline__ void split_h(float v, __half& h, __half& l) {
    h = __float2half(v);
    l = __float2half(v - __half2float(h));
}

__device__ __forceinline__ void cp_async16(uint32_t saddr, const void* gaddr) {
    asm volatile("cp.async.cg.shared.global [%0], [%1], 16;" :: "r"(saddr), "l"(gaddr));
}
#define CP_COMMIT() asm volatile("cp.async.commit_group;" ::: "memory")
#define CP_WAIT1()  asm volatile("cp.async.wait_group 1;" ::: "memory")

// mma.m16n8k16 f16 -> f32 accumulate
__device__ __forceinline__ void mma16816(float* c, const uint32_t* a, uint32_t b0, uint32_t b1) {
    asm volatile("mma.sync.aligned.m16n8k16.row.col.f32.f16.f16.f32 "
        "{%0,%1,%2,%3}, {%4,%5,%6,%7}, {%8,%9}, {%0,%1,%2,%3};"
        : "+f"(c[0]), "+f"(c[1]), "+f"(c[2]), "+f"(c[3])
        : "r"(a[0]), "r"(a[1]), "r"(a[2]), "r"(a[3]), "r"(b0), "r"(b1));
}

// ---------------- prep: transposed split weights ----------------------------
__global__ void wt_kernel(const float* __restrict__ cWl, const float* __restrict__ cWr,
                          const float* __restrict__ rWl, const float* __restrict__ rWr,
                          __half* __restrict__ Wh, __half* __restrict__ Wl_) {
    int idx = blockIdx.x * blockDim.x + threadIdx.x;
    const int total = L_ * 512 * 256;
    if (idx >= total) return;
    int l = idx / (512 * 256);
    int rem = idx - l * (512 * 256);
    int j = rem >> 8;            // output col 0..511
    int k = rem & 255;           // k index
    const float* sp; int col;
    if (j < 128)      { sp = cWl; col = j; }
    else if (j < 256) { sp = rWl; col = j - 128; }
    else if (j < 384) { sp = cWr; col = j - 256; }
    else              { sp = rWr; col = j - 384; }
    float v = sp[((size_t)l * 256 + k) * 128 + col];
    __half h, lo; split_h(v, h, lo);
    Wh[idx] = h; Wl_[idx] = lo;
}

__global__ void pwt_kernel(const float* __restrict__ preW,
                           __half* __restrict__ Wh, __half* __restrict__ Wl_) {
    int idx = blockIdx.x * blockDim.x + threadIdx.x;
    if (idx >= 256 * KPRE) return;
    int j = idx / KPRE;
    int k = idx - j * KPRE;
    float v = (k < INC) ? preW[k * 256 + j] : 0.f;
    __half h, lo; split_h(v, h, lo);
    Wh[idx] = h; Wl_[idx] = lo;
}

// ---------------- degrees ----------------------------------------------------
__global__ void degree_kernel(const int* __restrict__ src, const int* __restrict__ tgt,
                              float* degF, float* degR) {
    int e = blockIdx.x * blockDim.x + threadIdx.x;
    if (e >= E_) return;
    atomicAdd(&degF[tgt[e]], 1.f);
    atomicAdd(&degR[src[e]], 1.f);
}
__global__ void inv_kernel(float* degF, float* degR) {
    int n = blockIdx.x * blockDim.x + threadIdx.x;
    if (n >= N_) return;
    degF[n] = 1.f / fmaxf(degF[n], 1.f);
    degR[n] = 1.f / fmaxf(degR[n], 1.f);
}

// ---------------- feature construction (split fp16) --------------------------
__global__ void feat_kernel(const float* __restrict__ x_feat, const float* __restrict__ dim_feat,
                            const float* __restrict__ layout_feat, const float* __restrict__ tile_feat,
                            const float* __restrict__ opcode_embed,
                            const int* __restrict__ node_opcode, const int* __restrict__ batch,
                            __half* __restrict__ Fh, __half* __restrict__ Fl) {
    int idx = blockIdx.x * blockDim.x + threadIdx.x;
    const int total = M_ * KPRE;
    if (idx >= total) return;
    int m = idx / KPRE;
    int c = idx - m * KPRE;
    int s = m & 1;
    int n = m >> 1;
    float v;
    if (c < 53)       v = x_feat[n * 53 + c];
    else if (c < 85)  v = opcode_embed[node_opcode[n] * 32 + (c - 53)];
    else if (c < 223) v = dim_feat[n * 138 + (c - 85)];
    else if (c < 247) v = layout_feat[n * (S_ * 24) + s * 24 + (c - 223)];
    else if (c < 265) v = tile_feat[batch[n] * (S_ * 18) + s * 18 + (c - 247)];
    else              v = 0.f;
    __half h, lo; split_h(v, h, lo);
    Fh[idx] = h; Fl[idx] = lo;
}

// ---------------- split-fp16 HMMA GEMM ---------------------------------------
// Block tile 128x256, 8 warps (2 M x 4 N), warp tile 64x64.
// A: [M,K] row-major halves (hi/lo). B: [Nout,K] row-major halves (= B^T, "col" operand).
// 3-MMA scheme: acc += Ah*Bh + Al*Bh + Ah*Bl.
// mode 0 (pre): relu(acc + preb[col]) split -> Xh/Xl [M,256]
// mode 1 (layer): Yout[row*512 + bn + col] = acc
// SMEM per stage: Ah(128x40h=10240B) Al(10240) Bh(256x40h=20480) Bl(20480) = 61440B; 2 stages.
#define STG_B 61440
#define SMEM_TOTAL (2 * STG_B)

__global__ void __launch_bounds__(256, 1)
mma_gemm_k(const __half* __restrict__ Ah, const __half* __restrict__ Al,
           const __half* __restrict__ Bh, const __half* __restrict__ Bl,
           int M, int K, int mode, const float* __restrict__ preb,
           float* __restrict__ Yout, __half* __restrict__ Xh, __half* __restrict__ Xl) {
    extern __shared__ char smem[];
    const uint32_t sbase = smem_u32(smem);
    const int tid = threadIdx.x, wid = tid >> 5, lane = tid & 31;
    const int bm = blockIdx.x * 128;
    const int bn = blockIdx.y * 256;
    const int warpM = wid & 1, warpN = wid >> 1;
    const int m0 = warpM * 64, n0 = warpN * 64;
    const int g = lane >> 2, tg = lane & 3;
    const int KT = K >> 5;

    auto loadStage = [&](int kt, int s) {
        const uint32_t stB = sbase + s * STG_B;
        const int k0 = kt * 32;
#pragma unroll
        for (int n = 0; n < 12; n++) {
            int i = tid + n * 256;
            const __half* gp; uint32_t sa;
            if (i < 1024) {
                int which = i >> 9; int u = i & 511;
                int row = u >> 2, c = u & 3;
                int grow = bm + row; if (grow >= M) grow = M - 1;
                gp = (which ? Al : Ah) + (size_t)grow * K + k0 + c * 8;
                sa = stB + which * 10240 + row * 80 + c * 16;
            } else {
                int j = i - 1024;
                int which = j >> 10; int u = j & 1023;
                int row = u >> 2, c = u & 3;
                gp = (which ? Bl : Bh) + (size_t)(bn + row) * K + k0 + c * 8;
                sa = stB + 20480 + which * 20480 + row * 80 + c * 16;
            }
            cp_async16(sa, gp);
        }
    };

    float acc[4][8][4];
#pragma unroll
    for (int mt = 0; mt < 4; mt++)
#pragma unroll
        for (int nt = 0; nt < 8; nt++)
#pragma unroll
            for (int q = 0; q < 4; q++) acc[mt][nt][q] = 0.f;

    loadStage(0, 0); CP_COMMIT();
    loadStage(1, 1); CP_COMMIT();

    for (int kt = 0; kt < KT; kt++) {
        const int s = kt & 1;
        CP_WAIT1();
        __syncthreads();
        const char* st = smem + s * STG_B;
#pragma unroll
        for (int k16 = 0; k16 < 2; k16++) {
            uint32_t ah[4][4], al[4][4];
#pragma unroll
            for (int mt = 0; mt < 4; mt++) {
                int row = m0 + mt * 16 + g;
                int off = row * 80 + k16 * 32 + tg * 4;
                const char* pH = st + off;
                const char* pL = st + 10240 + off;
                ah[mt][0] = *(const uint32_t*)(pH);
                ah[mt][1] = *(const uint32_t*)(pH + 640);
                ah[mt][2] = *(const uint32_t*)(pH + 16);
                ah[mt][3] = *(const uint32_t*)(pH + 656);
                al[mt][0] = *(const uint32_t*)(pL);
                al[mt][1] = *(const uint32_t*)(pL + 640);
                al[mt][2] = *(const uint32_t*)(pL + 16);
                al[mt][3] = *(const uint32_t*)(pL + 656);
            }
#pragma unroll
            for (int nt = 0; nt < 8; nt++) {
                int nrow = n0 + nt * 8 + g;
                int boff = 20480 + nrow * 80 + k16 * 32 + tg * 4;
                uint32_t bh0 = *(const uint32_t*)(st + boff);
                uint32_t bh1 = *(const uint32_t*)(st + boff + 16);
                uint32_t bl0 = *(const uint32_t*)(st + 20480 + boff);
                uint32_t bl1 = *(const uint32_t*)(st + 20480 + boff + 16);
#pragma unroll
                for (int mt = 0; mt < 4; mt++) {
                    mma16816(acc[mt][nt], ah[mt], bh0, bh1);
                    mma16816(acc[mt][nt], al[mt], bh0, bh1);
                    mma16816(acc[mt][nt], ah[mt], bl0, bl1);
                }
            }
        }
        __syncthreads();
        if (kt + 2 < KT) loadStage(kt + 2, s);
        CP_COMMIT();
    }

    // Epilogue. c0,c1: (row=g, col=tg*2+{0,1}); c2,c3: row=g+8.
#pragma unroll
    for (int mt = 0; mt < 4; mt++) {
#pragma unroll
        for (int nt = 0; nt < 8; nt++) {
            int row = bm + m0 + mt * 16 + g;
            int colL = n0 + nt * 8 + tg * 2;       // 0..255 within block
            int col = bn + colL;
            float* c = acc[mt][nt];
            if (mode == 1) {
                if (row < M) {
                    float2 v = make_float2(c[0], c[1]);
                    *(float2*)(Yout + (size_t)row * 512 + col) = v;
                }
                if (row + 8 < M) {
                    float2 v = make_float2(c[2], c[3]);
                    *(float2*)(Yout + (size_t)(row + 8) * 512 + col) = v;
                }
            } else {
                float b0 = preb[col], b1 = preb[col + 1];
                if (row < M) {
                    float v0 = fmaxf(c[0] + b0, 0.f), v1 = fmaxf(c[1] + b1, 0.f);
                    __half h0, l0, h1, l1;
                    split_h(v0, h0, l0); split_h(v1, h1, l1);
                    __half2 hh; hh.x = h0; hh.y = h1;
                    __half2 ll; ll.x = l0; ll.y = l1;
                    *(__half2*)(Xh + (size_t)row * 256 + col) = hh;
                    *(__half2*)(Xl + (size_t)row * 256 + col) = ll;
                }
                if (row + 8 < M) {
                    float v0 = fmaxf(c[2] + b0, 0.f), v1 = fmaxf(c[3] + b1, 0.f);
                    __half h0, l0, h1, l1;
                    split_h(v0, h0, l0); split_h(v1, h1, l1);
                    __half2 hh; hh.x = h0; hh.y = h1;
                    __half2 ll; ll.x = l0; ll.y = l1;
                    *(__half2*)(Xh + (size_t)(row + 8) * 256 + col) = hh;
                    *(__half2*)(Xl + (size_t)(row + 8) * 256 + col) = ll;
                }
            }
        }
    }
}

// ---------------- edge scatter (both directions) ----------------------------
// Y row stride = 512 floats = 128 float4 per M-ROW. M-row of node n, sample smp
// is (2n + smp). Fwd messages: Y cols 0:128 (float4 0..31); rev: cols 128:256.
// Per edge we move S_*128 channels each direction: c = smp*32 + cc.
__global__ void scatter_kernel(const float4* __restrict__ Y4,
                               float4* __restrict__ AF, float4* __restrict__ AR,
                               const int* __restrict__ src, const int* __restrict__ tgt) {
    long idx = (long)blockIdx.x * blockDim.x + threadIdx.x;
    const long total = (long)E_ * 64;
    if (idx >= total) return;
    int e = (int)(idx >> 6);
    int c = (int)(idx & 63);
    int smp = c >> 5;            // sample 0/1
    int cc = c & 31;             // float4 within 128 channels
    int s = __ldg(src + e);
    int t = __ldg(tgt + e);
    size_t rs = (size_t)(2 * s + smp);
    size_t rt = (size_t)(2 * t + smp);
    float4 v = __ldg(&Y4[rs * 128 + cc]);
    red4(AF + rt * 32 + cc, v);
    float4 w = __ldg(&Y4[rt * 128 + 32 + cc]);
    red4(AR + rs * 32 + cc, w);
}

// ---------------- combine + relu + split-fp16 + (pool last 2 layers) --------
__global__ void combine_kernel(const float* __restrict__ Y, const float* __restrict__ AF,
                               const float* __restrict__ AR,
                               const float* __restrict__ invF, const float* __restrict__ invR,
                               const float* __restrict__ cb, const float* __restrict__ rb,
                               const float* __restrict__ headW, const int* __restrict__ batch,
                               float* __restrict__ pooled, int layer,
                               __half* __restrict__ Xh, __half* __restrict__ Xl) {
    int warp = (blockIdx.x * blockDim.x + threadIdx.x) >> 5;
    int lane = threadIdx.x & 31;
    if (warp >= M_) return;
    int m = warp;
    int n = m >> 1;
    int s = m & 1;
    const float iF = invF[n];
    const float iR = invR[n];
    const float4* ySelf = (const float4*)(Y + (size_t)m * 512 + 256); // conv self | rev self
    const float4* aF = (const float4*)(AF + (size_t)m * 128);
    const float4* aR = (const float4*)(AR + (size_t)m * 128);
    const int doPool = (layer >= L_ - 2);
    const int writeX = (layer < L_ - 1);
    const int hoff = (layer - (L_ - 2)) * 256;
    float dot = 0.f;
#pragma unroll
    for (int u = 0; u < 2; u++) {
        int j4 = lane * 2 + u;   // 0..63 (float4 index in 256-ch output)
        float4 sv = __ldg(ySelf + j4);
        float4 av, bv; float sc;
        if (j4 < 32) { av = aF[j4]; sc = iF; bv = *(const float4*)(cb + j4 * 4); }
        else         { av = aR[j4 - 32]; sc = iR; bv = *(const float4*)(rb + (j4 - 32) * 4); }
        float v0 = fmaxf(sv.x + av.x * sc + bv.x, 0.f);
        float v1 = fmaxf(sv.y + av.y * sc + bv.y, 0.f);
        float v2 = fmaxf(sv.z + av.z * sc + bv.z, 0.f);
        float v3 = fmaxf(sv.w + av.w * sc + bv.w, 0.f);
        if (writeX) {
            __half h0, l0, h1, l1, h2, l2, h3, l3;
            split_h(v0, h0, l0); split_h(v1, h1, l1);
            split_h(v2, h2, l2); split_h(v3, h3, l3);
            __half2 ha; ha.x = h0; ha.y = h1;
            __half2 hb; hb.x = h2; hb.y = h3;
            __half2 la; la.x = l0; la.y = l1;
            __half2 lb; lb.x = l2; lb.y = l3;
            *(__half2*)(Xh + (size_t)m * 256 + j4 * 4)     = ha;
            *(__half2*)(Xh + (size_t)m * 256 + j4 * 4 + 2) = hb;
            *(__half2*)(Xl + (size_t)m * 256 + j4 * 4)     = la;
            *(__half2*)(Xl + (size_t)m * 256 + j4 * 4 + 2) = lb;
        }
        if (doPool) {
            float4 hw = __ldg((const float4*)(headW + hoff) + j4);
            dot += v0 * hw.x + v1 * hw.y + v2 * hw.z + v3 * hw.w;
        }
    }
    if (doPool) {
#pragma unroll
        for (int o = 16; o; o >>= 1) dot += __shfl_down_sync(0xffffffffu, dot, o);
        if (lane == 0) atomicAdd(&pooled[s * G_ + batch[n]], dot);
    }
}

// ---------------- final ------------------------------------------------------
__global__ void final_kernel(const float* __restrict__ pooled, const float* __restrict__ headb,
                             float* __restrict__ out) {
    int i = threadIdx.x;
    if (i < S_ * G_) {
        int g = i >> 1;
        int s = i & 1;
        out[i] = pooled[s * G_ + g] + headb[0];
    }
}

// ---------------- launch -----------------------------------------------------
extern "C" void kernel_launch(void* const* d_in, const int* in_sizes, int n_in,
                              void* d_out, int out_size) {
    const float* x_feat       = (const float*)d_in[0];
    const float* dim_feat     = (const float*)d_in[1];
    const float* layout_feat  = (const float*)d_in[2];
    const float* tile_feat    = (const float*)d_in[3];
    const float* opcode_embed = (const float*)d_in[4];
    const float* preW         = (const float*)d_in[5];
    const float* preb         = (const float*)d_in[6];
    const float* convWl       = (const float*)d_in[7];
    const float* convWr       = (const float*)d_in[8];
    const float* convb        = (const float*)d_in[9];
    const float* revWl        = (const float*)d_in[10];
    const float* revWr        = (const float*)d_in[11];
    const float* revb         = (const float*)d_in[12];
    const float* headW        = (const float*)d_in[13];
    const float* headb        = (const float*)d_in[14];
    const int*   node_opcode  = (const int*)d_in[15];
    const int*   batch        = (const int*)d_in[16];
    const int*   edge_index   = (const int*)d_in[17];
    const int* src = edge_index;
    const int* tgt = edge_index + E_;

    float *Y, *AF, *AR, *degF, *degR, *pooled;
    __half *Xh0, *Xl0, *Xh1, *Xl1, *Fh, *Fl, *Wth, *Wtl, *PWh, *PWl;
    cudaGetSymbolAddress((void**)&Y,    g_Y);
    cudaGetSymbolAddress((void**)&Xh0,  g_Xh0);
    cudaGetSymbolAddress((void**)&Xl0,  g_Xl0);
    cudaGetSymbolAddress((void**)&Xh1,  g_Xh1);
    cudaGetSymbolAddress((void**)&Xl1,  g_Xl1);
    cudaGetSymbolAddress((void**)&Fh,   g_Fh);
    cudaGetSymbolAddress((void**)&Fl,   g_Fl);
    cudaGetSymbolAddress((void**)&AF,   g_AF);
    cudaGetSymbolAddress((void**)&AR,   g_AR);
    cudaGetSymbolAddress((void**)&Wth,  g_Wth);
    cudaGetSymbolAddress((void**)&Wtl,  g_Wtl);
    cudaGetSymbolAddress((void**)&PWh,  g_PWh);
    cudaGetSymbolAddress((void**)&PWl,  g_PWl);
    cudaGetSymbolAddress((void**)&degF, g_degF);
    cudaGetSymbolAddress((void**)&degR, g_degR);
    cudaGetSymbolAddress((void**)&pooled, g_pooled);

    cudaFuncSetAttribute(mma_gemm_k, cudaFuncAttributeMaxDynamicSharedMemorySize, SMEM_TOTAL);

    // prep
    wt_kernel<<<(L_ * 512 * 256 + 255) / 256, 256>>>(convWl, convWr, revWl, revWr, Wth, Wtl);
    pwt_kernel<<<(256 * KPRE + 255) / 256, 256>>>(preW, PWh, PWl);
    cudaMemsetAsync(degF, 0, (size_t)N_ * 4);
    cudaMemsetAsync(degR, 0, (size_t)N_ * 4);
    cudaMemsetAsync(pooled, 0, (size_t)S_ * G_ * 4);
    degree_kernel<<<(E_ + 255) / 256, 256>>>(src, tgt, degF, degR);
    inv_kernel<<<(N_ + 255) / 256, 256>>>(degF, degR);

    // features + pre-layer GEMM (K=320, Nout=256 -> Xh0/Xl0)
    feat_kernel<<<(int)(((size_t)M_ * KPRE + 255) / 256), 256>>>(
        x_feat, dim_feat, layout_feat, tile_feat, opcode_embed, node_opcode, batch, Fh, Fl);
    {
        dim3 gr((M_ + 127) / 128, 1);
        mma_gemm_k<<<gr, 256, SMEM_TOTAL>>>(Fh, Fl, PWh, PWl, M_, KPRE, 0,
                                            preb, nullptr, Xh0, Xl0);
    }

    __half *curH = Xh0, *curL = Xl0, *nxtH = Xh1, *nxtL = Xl1;
    for (int l = 0; l < L_; l++) {
        cudaMemsetAsync(AF, 0, (size_t)M_ * 128 * 4);
        cudaMemsetAsync(AR, 0, (size_t)M_ * 128 * 4);
        dim3 gr((M_ + 127) / 128, 2);
        mma_gemm_k<<<gr, 256, SMEM_TOTAL>>>(curH, curL,
                                            Wth + (size_t)l * 512 * 256,
                                            Wtl + (size_t)l * 512 * 256,
                                            M_, 256, 1, nullptr, Y, nullptr, nullptr);
        scatter_kernel<<<(int)(((long)E_ * 64 + 255) / 256), 256>>>(
            (const float4*)Y, (float4*)AF, (float4*)AR, src, tgt);
        combine_kernel<<<(M_ * 32 + 255) / 256, 256>>>(
            Y, AF, AR, degF, degR, convb + l * 128, revb + l * 128,
            headW, batch, pooled, l, nxtH, nxtL);
        __half* t;
        t = curH; curH = nxtH; nxtH = t;
        t = curL; curL = nxtL; nxtL = t;
    }

    final_kernel<<<1, 32>>>(pooled, headb, (float*)d_out);
}

// round 14
// speedup vs baseline: 2.1622x; 1.2365x over previous
#include <cuda_runtime.h>
#include <cuda_fp16.h>
#include <cstdint>

// Problem constants
#define N_   100000
#define S_   2
#define G_   8
#define E_   400000
#define L_   4
#define INC  265
#define KPRE 288          // padded pre-layer K (9 chunks of 32)
#define M_   (N_ * S_)    // 200000 rows

// ---------------- scratch (device globals; no allocation allowed) ----------
__device__ float   g_Y  [(size_t)M_ * 512];     // layer GEMM out (fp32)
__device__ __half  g_Xh0[(size_t)M_ * 256];
__device__ __half  g_Xl0[(size_t)M_ * 256];
__device__ __half  g_Xh1[(size_t)M_ * 256];
__device__ __half  g_Xl1[(size_t)M_ * 256];
__device__ __half  g_Fh [(size_t)M_ * KPRE];
__device__ __half  g_Fl [(size_t)M_ * KPRE];
__device__ __half  g_Wth[(size_t)L_ * 512 * 256];  // W^T hi: [l][out col j][k]
__device__ __half  g_Wtl[(size_t)L_ * 512 * 256];
__device__ __half  g_PWh[(size_t)256 * KPRE];      // preW^T hi [256][288]
__device__ __half  g_PWl[(size_t)256 * KPRE];
__device__ float g_invF[N_];
__device__ float g_invR[N_];
__device__ int   g_degFi[N_];
__device__ int   g_degRi[N_];
__device__ int   g_rowF[N_ + 1];
__device__ int   g_rowR[N_ + 1];
__device__ int   g_curF[N_];
__device__ int   g_curR[N_];
__device__ int   g_colF[E_];
__device__ int   g_colR[E_];
__device__ float g_pooled[S_ * G_];

// ---------------- helpers ----------------------------------------------------
__device__ __forceinline__ uint32_t smem_u32(const void* p) {
    uint32_t a;
    asm("{ .reg .u64 t; cvta.to.shared.u64 t, %1; cvt.u32.u64 %0, t; }" : "=r"(a) : "l"(p));
    return a;
}

__device__ __forceinline__ void split_h(float v, __half& h, __half& l) {
    h = __float2half(v);
    l = __float2half(v - __half2float(h));
}

__device__ __forceinline__ void cp_async16(uint32_t saddr, const void* gaddr) {
    asm volatile("cp.async.cg.shared.global [%0], [%1], 16;" :: "r"(saddr), "l"(gaddr));
}
#define CP_COMMIT() asm volatile("cp.async.commit_group;" ::: "memory")
#define CP_WAIT1()  asm volatile("cp.async.wait_group 1;" ::: "memory")

// mma.m16n8k16 f16 -> f32 accumulate
__device__ __forceinline__ void mma16816(float* c, const uint32_t* a, uint32_t b0, uint32_t b1) {
    asm volatile("mma.sync.aligned.m16n8k16.row.col.f32.f16.f16.f32 "
        "{%0,%1,%2,%3}, {%4,%5,%6,%7}, {%8,%9}, {%0,%1,%2,%3};"
        : "+f"(c[0]), "+f"(c[1]), "+f"(c[2]), "+f"(c[3])
        : "r"(a[0]), "r"(a[1]), "r"(a[2]), "r"(a[3]), "r"(b0), "r"(b1));
}

// ---------------- prep: transposed split weights ----------------------------
__global__ void wt_kernel(const float* __restrict__ cWl, const float* __restrict__ cWr,
                          const float* __restrict__ rWl, const float* __restrict__ rWr,
                          __half* __restrict__ Wh, __half* __restrict__ Wl_) {
    int idx = blockIdx.x * blockDim.x + threadIdx.x;
    const int total = L_ * 512 * 256;
    if (idx >= total) return;
    int l = idx / (512 * 256);
    int rem = idx - l * (512 * 256);
    int j = rem >> 8;            // output col 0..511
    int k = rem & 255;           // k index
    const float* sp; int col;
    if (j < 128)      { sp = cWl; col = j; }
    else if (j < 256) { sp = rWl; col = j - 128; }
    else if (j < 384) { sp = cWr; col = j - 256; }
    else              { sp = rWr; col = j - 384; }
    float v = sp[((size_t)l * 256 + k) * 128 + col];
    __half h, lo; split_h(v, h, lo);
    Wh[idx] = h; Wl_[idx] = lo;
}

__global__ void pwt_kernel(const float* __restrict__ preW,
                           __half* __restrict__ Wh, __half* __restrict__ Wl_) {
    int idx = blockIdx.x * blockDim.x + threadIdx.x;
    if (idx >= 256 * KPRE) return;
    int j = idx / KPRE;
    int k = idx - j * KPRE;
    float v = (k < INC) ? preW[k * 256 + j] : 0.f;
    __half h, lo; split_h(v, h, lo);
    Wh[idx] = h; Wl_[idx] = lo;
}

// ---------------- degrees + CSR build ----------------------------------------
__global__ void degi_kernel(const int* __restrict__ src, const int* __restrict__ tgt,
                            int* degF, int* degR) {
    int e = blockIdx.x * blockDim.x + threadIdx.x;
    if (e >= E_) return;
    atomicAdd(&degF[tgt[e]], 1);
    atomicAdd(&degR[src[e]], 1);
}

__global__ void inv_kernel(const int* __restrict__ dF, const int* __restrict__ dR,
                           float* invF, float* invR) {
    int n = blockIdx.x * blockDim.x + threadIdx.x;
    if (n >= N_) return;
    invF[n] = 1.f / fmaxf((float)dF[n], 1.f);
    invR[n] = 1.f / fmaxf((float)dR[n], 1.f);
}

// Exclusive scan: one block, 1024 threads, chunked.
__global__ void scan_kernel(const int* __restrict__ deg, int* __restrict__ rowptr, int n) {
    __shared__ int ssum[1024];
    const int t = threadIdx.x;
    const int chunk = (n + 1023) >> 10;
    const int b = t * chunk;
    const int e = min(b + chunk, n);
    int s = 0;
    for (int i = b; i < e; i++) s += deg[i];
    ssum[t] = s;
    __syncthreads();
    for (int o = 1; o < 1024; o <<= 1) {
        int x = (t >= o) ? ssum[t - o] : 0;
        __syncthreads();
        ssum[t] += x;
        __syncthreads();
    }
    int run = ssum[t] - s;   // exclusive prefix of this chunk
    for (int i = b; i < e; i++) { rowptr[i] = run; run += deg[i]; }
    if (t == 1023) rowptr[n] = run;
}

__global__ void fill_kernel(const int* __restrict__ src, const int* __restrict__ tgt,
                            int* curF, int* curR,
                            int* __restrict__ colF, int* __restrict__ colR) {
    int e = blockIdx.x * blockDim.x + threadIdx.x;
    if (e >= E_) return;
    int s = src[e], t = tgt[e];
    int p = atomicAdd(&curF[t], 1);
    colF[p] = s;
    int q = atomicAdd(&curR[s], 1);
    colR[q] = t;
}

// ---------------- feature construction (split fp16) --------------------------
__global__ void feat_kernel(const float* __restrict__ x_feat, const float* __restrict__ dim_feat,
                            const float* __restrict__ layout_feat, const float* __restrict__ tile_feat,
                            const float* __restrict__ opcode_embed,
                            const int* __restrict__ node_opcode, const int* __restrict__ batch,
                            __half* __restrict__ Fh, __half* __restrict__ Fl) {
    int idx = blockIdx.x * blockDim.x + threadIdx.x;
    const int total = M_ * KPRE;
    if (idx >= total) return;
    int m = idx / KPRE;
    int c = idx - m * KPRE;
    int s = m & 1;
    int n = m >> 1;
    float v;
    if (c < 53)       v = x_feat[n * 53 + c];
    else if (c < 85)  v = opcode_embed[node_opcode[n] * 32 + (c - 53)];
    else if (c < 223) v = dim_feat[n * 138 + (c - 85)];
    else if (c < 247) v = layout_feat[n * (S_ * 24) + s * 24 + (c - 223)];
    else if (c < 265) v = tile_feat[batch[n] * (S_ * 18) + s * 18 + (c - 247)];
    else              v = 0.f;
    __half h, lo; split_h(v, h, lo);
    Fh[idx] = h; Fl[idx] = lo;
}

// ---------------- split-fp16 HMMA GEMM ---------------------------------------
// Block tile 128x256, 8 warps (2 M x 4 N), warp tile 64x64.
// A: [M,K] row-major halves (hi/lo). B: [Nout,K] row-major halves (= B^T, "col" operand).
// 3-MMA scheme: acc += Ah*Bh + Al*Bh + Ah*Bl.
// mode 0 (pre): relu(acc + preb[col]) split -> Xh/Xl [M,256]
// mode 1 (layer): Yout[row*512 + bn + col] = acc
// SMEM per stage: Ah(128x40h=10240B) Al(10240) Bh(256x40h=20480) Bl(20480) = 61440B; 2 stages.
#define STG_B 61440
#define SMEM_TOTAL (2 * STG_B)

__global__ void __launch_bounds__(256, 1)
mma_gemm_k(const __half* __restrict__ Ah, const __half* __restrict__ Al,
           const __half* __restrict__ Bh, const __half* __restrict__ Bl,
           int M, int K, int mode, const float* __restrict__ preb,
           float* __restrict__ Yout, __half* __restrict__ Xh, __half* __restrict__ Xl) {
    extern __shared__ char smem[];
    const uint32_t sbase = smem_u32(smem);
    const int tid = threadIdx.x, wid = tid >> 5, lane = tid & 31;
    const int bm = blockIdx.x * 128;
    const int bn = blockIdx.y * 256;
    const int warpM = wid & 1, warpN = wid >> 1;
    const int m0 = warpM * 64, n0 = warpN * 64;
    const int g = lane >> 2, tg = lane & 3;
    const int KT = K >> 5;

    auto loadStage = [&](int kt, int s) {
        const uint32_t stB = sbase + s * STG_B;
        const int k0 = kt * 32;
#pragma unroll
        for (int n = 0; n < 12; n++) {
            int i = tid + n * 256;
            const __half* gp; uint32_t sa;
            if (i < 1024) {
                int which = i >> 9; int u = i & 511;
                int row = u >> 2, c = u & 3;
                int grow = bm + row; if (grow >= M) grow = M - 1;
                gp = (which ? Al : Ah) + (size_t)grow * K + k0 + c * 8;
                sa = stB + which * 10240 + row * 80 + c * 16;
            } else {
                int j = i - 1024;
                int which = j >> 10; int u = j & 1023;
                int row = u >> 2, c = u & 3;
                gp = (which ? Bl : Bh) + (size_t)(bn + row) * K + k0 + c * 8;
                sa = stB + 20480 + which * 20480 + row * 80 + c * 16;
            }
            cp_async16(sa, gp);
        }
    };

    float acc[4][8][4];
#pragma unroll
    for (int mt = 0; mt < 4; mt++)
#pragma unroll
        for (int nt = 0; nt < 8; nt++)
#pragma unroll
            for (int q = 0; q < 4; q++) acc[mt][nt][q] = 0.f;

    loadStage(0, 0); CP_COMMIT();
    loadStage(1, 1); CP_COMMIT();

    for (int kt = 0; kt < KT; kt++) {
        const int s = kt & 1;
        CP_WAIT1();
        __syncthreads();
        const char* st = smem + s * STG_B;
#pragma unroll
        for (int k16 = 0; k16 < 2; k16++) {
            uint32_t ah[4][4], al[4][4];
#pragma unroll
            for (int mt = 0; mt < 4; mt++) {
                int row = m0 + mt * 16 + g;
                int off = row * 80 + k16 * 32 + tg * 4;
                const char* pH = st + off;
                const char* pL = st + 10240 + off;
                ah[mt][0] = *(const uint32_t*)(pH);
                ah[mt][1] = *(const uint32_t*)(pH + 640);
                ah[mt][2] = *(const uint32_t*)(pH + 16);
                ah[mt][3] = *(const uint32_t*)(pH + 656);
                al[mt][0] = *(const uint32_t*)(pL);
                al[mt][1] = *(const uint32_t*)(pL + 640);
                al[mt][2] = *(const uint32_t*)(pL + 16);
                al[mt][3] = *(const uint32_t*)(pL + 656);
            }
#pragma unroll
            for (int nt = 0; nt < 8; nt++) {
                int nrow = n0 + nt * 8 + g;
                int boff = 20480 + nrow * 80 + k16 * 32 + tg * 4;
                uint32_t bh0 = *(const uint32_t*)(st + boff);
                uint32_t bh1 = *(const uint32_t*)(st + boff + 16);
                uint32_t bl0 = *(const uint32_t*)(st + 20480 + boff);
                uint32_t bl1 = *(const uint32_t*)(st + 20480 + boff + 16);
#pragma unroll
                for (int mt = 0; mt < 4; mt++) {
                    mma16816(acc[mt][nt], ah[mt], bh0, bh1);
                    mma16816(acc[mt][nt], al[mt], bh0, bh1);
                    mma16816(acc[mt][nt], ah[mt], bl0, bl1);
                }
            }
        }
        __syncthreads();
        if (kt + 2 < KT) loadStage(kt + 2, s);
        CP_COMMIT();
    }

    // Epilogue. c0,c1: (row=g, col=tg*2+{0,1}); c2,c3: row=g+8.
#pragma unroll
    for (int mt = 0; mt < 4; mt++) {
#pragma unroll
        for (int nt = 0; nt < 8; nt++) {
            int row = bm + m0 + mt * 16 + g;
            int colL = n0 + nt * 8 + tg * 2;       // 0..255 within block
            int col = bn + colL;
            float* c = acc[mt][nt];
            if (mode == 1) {
                if (row < M) {
                    float2 v = make_float2(c[0], c[1]);
                    *(float2*)(Yout + (size_t)row * 512 + col) = v;
                }
                if (row + 8 < M) {
                    float2 v = make_float2(c[2], c[3]);
                    *(float2*)(Yout + (size_t)(row + 8) * 512 + col) = v;
                }
            } else {
                float b0 = preb[col], b1 = preb[col + 1];
                if (row < M) {
                    float v0 = fmaxf(c[0] + b0, 0.f), v1 = fmaxf(c[1] + b1, 0.f);
                    __half h0, l0, h1, l1;
                    split_h(v0, h0, l0); split_h(v1, h1, l1);
                    __half2 hh; hh.x = h0; hh.y = h1;
                    __half2 ll; ll.x = l0; ll.y = l1;
                    *(__half2*)(Xh + (size_t)row * 256 + col) = hh;
                    *(__half2*)(Xl + (size_t)row * 256 + col) = ll;
                }
                if (row + 8 < M) {
                    float v0 = fmaxf(c[2] + b0, 0.f), v1 = fmaxf(c[3] + b1, 0.f);
                    __half h0, l0, h1, l1;
                    split_h(v0, h0, l0); split_h(v1, h1, l1);
                    __half2 hh; hh.x = h0; hh.y = h1;
                    __half2 ll; ll.x = l0; ll.y = l1;
                    *(__half2*)(Xh + (size_t)(row + 8) * 256 + col) = hh;
                    *(__half2*)(Xl + (size_t)(row + 8) * 256 + col) = ll;
                }
            }
        }
    }
}

// ---------------- CSR gather + combine + relu + split + pool -----------------
// One warp per m-row. Y row = 128 float4: [0:32)=fwd msg, [32:64)=rev msg,
// [64:96)=conv self, [96:128)=rev self. Lane handles 4 fwd ch (lane*4..)
// and 4 rev ch (128+lane*4..).
__global__ void gather_combine(const float4* __restrict__ Y4,
                               const int* __restrict__ rowF, const int* __restrict__ colF,
                               const int* __restrict__ rowR, const int* __restrict__ colR,
                               const float* __restrict__ invF, const float* __restrict__ invR,
                               const float* __restrict__ cb, const float* __restrict__ rb,
                               const float* __restrict__ headW, const int* __restrict__ batch,
                               float* __restrict__ pooled, int layer,
                               __half* __restrict__ Xh, __half* __restrict__ Xl) {
    int warp = (blockIdx.x * blockDim.x + threadIdx.x) >> 5;
    int lane = threadIdx.x & 31;
    if (warp >= M_) return;
    const int m = warp;
    const int n = m >> 1;
    const int smp = m & 1;

    float4 aF = make_float4(0.f, 0.f, 0.f, 0.f);
    {
        int beg = __ldg(rowF + n), end = __ldg(rowF + n + 1);
        for (int j = beg; j < end; j++) {
            int sn = __ldg(colF + j);
            float4 v = __ldg(Y4 + (size_t)(2 * sn + smp) * 128 + lane);
            aF.x += v.x; aF.y += v.y; aF.z += v.z; aF.w += v.w;
        }
    }
    float4 aR = make_float4(0.f, 0.f, 0.f, 0.f);
    {
        int beg = __ldg(rowR + n), end = __ldg(rowR + n + 1);
        for (int j = beg; j < end; j++) {
            int tn = __ldg(colR + j);
            float4 v = __ldg(Y4 + (size_t)(2 * tn + smp) * 128 + 32 + lane);
            aR.x += v.x; aR.y += v.y; aR.z += v.z; aR.w += v.w;
        }
    }

    const float iF = invF[n];
    const float iR = invR[n];
    const float4* yRow = Y4 + (size_t)m * 128;
    float4 sF = __ldg(yRow + 64 + lane);
    float4 sR = __ldg(yRow + 96 + lane);
    float4 bF = *(const float4*)(cb + lane * 4);
    float4 bR = *(const float4*)(rb + lane * 4);

    float f0 = fmaxf(sF.x + aF.x * iF + bF.x, 0.f);
    float f1 = fmaxf(sF.y + aF.y * iF + bF.y, 0.f);
    float f2 = fmaxf(sF.z + aF.z * iF + bF.z, 0.f);
    float f3 = fmaxf(sF.w + aF.w * iF + bF.w, 0.f);
    float r0 = fmaxf(sR.x + aR.x * iR + bR.x, 0.f);
    float r1 = fmaxf(sR.y + aR.y * iR + bR.y, 0.f);
    float r2 = fmaxf(sR.z + aR.z * iR + bR.z, 0.f);
    float r3 = fmaxf(sR.w + aR.w * iR + bR.w, 0.f);

    if (layer < L_ - 1) {
        __half h, l;
        uint32_t hF[2], lF[2], hR[2], lR[2];
        __half2 t;
        split_h(f0, h, l); t.x = h; __half2 tl; tl.x = l;
        split_h(f1, h, l); t.y = h; tl.y = l; hF[0] = *(uint32_t*)&t; lF[0] = *(uint32_t*)&tl;
        split_h(f2, h, l); t.x = h; tl.x = l;
        split_h(f3, h, l); t.y = h; tl.y = l; hF[1] = *(uint32_t*)&t; lF[1] = *(uint32_t*)&tl;
        split_h(r0, h, l); t.x = h; tl.x = l;
        split_h(r1, h, l); t.y = h; tl.y = l; hR[0] = *(uint32_t*)&t; lR[0] = *(uint32_t*)&tl;
        split_h(r2, h, l); t.x = h; tl.x = l;
        split_h(r3, h, l); t.y = h; tl.y = l; hR[1] = *(uint32_t*)&t; lR[1] = *(uint32_t*)&tl;
        *(uint2*)(Xh + (size_t)m * 256 + lane * 4)       = make_uint2(hF[0], hF[1]);
        *(uint2*)(Xl + (size_t)m * 256 + lane * 4)       = make_uint2(lF[0], lF[1]);
        *(uint2*)(Xh + (size_t)m * 256 + 128 + lane * 4) = make_uint2(hR[0], hR[1]);
        *(uint2*)(Xl + (size_t)m * 256 + 128 + lane * 4) = make_uint2(lR[0], lR[1]);
    }

    if (layer >= L_ - 2) {
        const int hoff = (layer - (L_ - 2)) * 256;
        float4 wF = __ldg((const float4*)(headW + hoff) + lane);
        float4 wR = __ldg((const float4*)(headW + hoff + 128) + lane);
        float dot = f0 * wF.x + f1 * wF.y + f2 * wF.z + f3 * wF.w
                  + r0 * wR.x + r1 * wR.y + r2 * wR.z + r3 * wR.w;
#pragma unroll
        for (int o = 16; o; o >>= 1) dot += __shfl_down_sync(0xffffffffu, dot, o);
        if (lane == 0) atomicAdd(&pooled[smp * G_ + batch[n]], dot);
    }
}

// ---------------- final ------------------------------------------------------
__global__ void final_kernel(const float* __restrict__ pooled, const float* __restrict__ headb,
                             float* __restrict__ out) {
    int i = threadIdx.x;
    if (i < S_ * G_) {
        int g = i >> 1;
        int s = i & 1;
        out[i] = pooled[s * G_ + g] + headb[0];
    }
}

// ---------------- launch -----------------------------------------------------
extern "C" void kernel_launch(void* const* d_in, const int* in_sizes, int n_in,
                              void* d_out, int out_size) {
    const float* x_feat       = (const float*)d_in[0];
    const float* dim_feat     = (const float*)d_in[1];
    const float* layout_feat  = (const float*)d_in[2];
    const float* tile_feat    = (const float*)d_in[3];
    const float* opcode_embed = (const float*)d_in[4];
    const float* preW         = (const float*)d_in[5];
    const float* preb         = (const float*)d_in[6];
    const float* convWl       = (const float*)d_in[7];
    const float* convWr       = (const float*)d_in[8];
    const float* convb        = (const float*)d_in[9];
    const float* revWl        = (const float*)d_in[10];
    const float* revWr        = (const float*)d_in[11];
    const float* revb         = (const float*)d_in[12];
    const float* headW        = (const float*)d_in[13];
    const float* headb        = (const float*)d_in[14];
    const int*   node_opcode  = (const int*)d_in[15];
    const int*   batch        = (const int*)d_in[16];
    const int*   edge_index   = (const int*)d_in[17];
    const int* src = edge_index;
    const int* tgt = edge_index + E_;

    float *Y, *invF, *invR, *pooled;
    int *degFi, *degRi, *rowF, *rowR, *curF, *curR, *colF, *colR;
    __half *Xh0, *Xl0, *Xh1, *Xl1, *Fh, *Fl, *Wth, *Wtl, *PWh, *PWl;
    cudaGetSymbolAddress((void**)&Y,    g_Y);
    cudaGetSymbolAddress((void**)&Xh0,  g_Xh0);
    cudaGetSymbolAddress((void**)&Xl0,  g_Xl0);
    cudaGetSymbolAddress((void**)&Xh1,  g_Xh1);
    cudaGetSymbolAddress((void**)&Xl1,  g_Xl1);
    cudaGetSymbolAddress((void**)&Fh,   g_Fh);
    cudaGetSymbolAddress((void**)&Fl,   g_Fl);
    cudaGetSymbolAddress((void**)&Wth,  g_Wth);
    cudaGetSymbolAddress((void**)&Wtl,  g_Wtl);
    cudaGetSymbolAddress((void**)&PWh,  g_PWh);
    cudaGetSymbolAddress((void**)&PWl,  g_PWl);
    cudaGetSymbolAddress((void**)&invF, g_invF);
    cudaGetSymbolAddress((void**)&invR, g_invR);
    cudaGetSymbolAddress((void**)&degFi, g_degFi);
    cudaGetSymbolAddress((void**)&degRi, g_degRi);
    cudaGetSymbolAddress((void**)&rowF, g_rowF);
    cudaGetSymbolAddress((void**)&rowR, g_rowR);
    cudaGetSymbolAddress((void**)&curF, g_curF);
    cudaGetSymbolAddress((void**)&curR, g_curR);
    cudaGetSymbolAddress((void**)&colF, g_colF);
    cudaGetSymbolAddress((void**)&colR, g_colR);
    cudaGetSymbolAddress((void**)&pooled, g_pooled);

    cudaFuncSetAttribute(mma_gemm_k, cudaFuncAttributeMaxDynamicSharedMemorySize, SMEM_TOTAL);

    // prep: weights
    wt_kernel<<<(L_ * 512 * 256 + 255) / 256, 256>>>(convWl, convWr, revWl, revWr, Wth, Wtl);
    pwt_kernel<<<(256 * KPRE + 255) / 256, 256>>>(preW, PWh, PWl);

    // prep: degrees + CSR
    cudaMemsetAsync(degFi, 0, (size_t)N_ * 4);
    cudaMemsetAsync(degRi, 0, (size_t)N_ * 4);
    cudaMemsetAsync(pooled, 0, (size_t)S_ * G_ * 4);
    degi_kernel<<<(E_ + 255) / 256, 256>>>(src, tgt, degFi, degRi);
    inv_kernel<<<(N_ + 255) / 256, 256>>>(degFi, degRi, invF, invR);
    scan_kernel<<<1, 1024>>>(degFi, rowF, N_);
    scan_kernel<<<1, 1024>>>(degRi, rowR, N_);
    cudaMemcpyAsync(curF, rowF, (size_t)N_ * 4, cudaMemcpyDeviceToDevice);
    cudaMemcpyAsync(curR, rowR, (size_t)N_ * 4, cudaMemcpyDeviceToDevice);
    fill_kernel<<<(E_ + 255) / 256, 256>>>(src, tgt, curF, curR, colF, colR);

    // features + pre-layer GEMM (K=288, Nout=256 -> Xh0/Xl0)
    feat_kernel<<<(int)(((size_t)M_ * KPRE + 255) / 256), 256>>>(
        x_feat, dim_feat, layout_feat, tile_feat, opcode_embed, node_opcode, batch, Fh, Fl);
    {
        dim3 gr((M_ + 127) / 128, 1);
        mma_gemm_k<<<gr, 256, SMEM_TOTAL>>>(Fh, Fl, PWh, PWl, M_, KPRE, 0,
                                            preb, nullptr, Xh0, Xl0);
    }

    __half *curH = Xh0, *curL = Xl0, *nxtH = Xh1, *nxtL = Xl1;
    for (int l = 0; l < L_; l++) {
        dim3 gr((M_ + 127) / 128, 2);
        mma_gemm_k<<<gr, 256, SMEM_TOTAL>>>(curH, curL,
                                            Wth + (size_t)l * 512 * 256,
                                            Wtl + (size_t)l * 512 * 256,
                                            M_, 256, 1, nullptr, Y, nullptr, nullptr);
        gather_combine<<<(M_ * 32 + 255) / 256, 256>>>(
            (const float4*)Y, rowF, colF, rowR, colR, invF, invR,
            convb + l * 128, revb + l * 128, headW, batch, pooled, l, nxtH, nxtL);
        __half* t;
        t = curH; curH = nxtH; nxtH = t;
        t = curL; curL = nxtL; nxtL = t;
    }

    final_kernel<<<1, 32>>>(pooled, headb, (float*)d_out);
}

// round 16
// speedup vs baseline: 2.6201x; 1.2117x over previous
#include <cuda_runtime.h>
#include <cuda_fp16.h>
#include <cstdint>

// Problem constants
#define N_   100000
#define S_   2
#define G_   8
#define E_   400000
#define L_   4
#define INC  265
#define KPRE 288          // padded pre-layer K (9 chunks of 32)
#define M_   (N_ * S_)    // 200000 rows

// ---------------- scratch (device globals; no allocation allowed) ----------
__device__ float   g_Y  [(size_t)M_ * 512];     // layer GEMM out (fp32)
__device__ __half  g_Xh0[(size_t)M_ * 256];
__device__ __half  g_Xh1[(size_t)M_ * 256];
__device__ __half  g_Fh [(size_t)M_ * KPRE];
__device__ __half  g_Wth[(size_t)L_ * 512 * 256];  // W^T hi: [l][out col j][k]
__device__ __half  g_Wtl[(size_t)L_ * 512 * 256];
__device__ __half  g_PWh[(size_t)256 * KPRE];      // preW^T hi [256][288]
__device__ __half  g_PWl[(size_t)256 * KPRE];
__device__ float g_invF[N_];
__device__ float g_invR[N_];
__device__ int   g_degFi[N_];
__device__ int   g_degRi[N_];
__device__ int   g_rowF[N_ + 1];
__device__ int   g_rowR[N_ + 1];
__device__ int   g_curF[N_];
__device__ int   g_curR[N_];
__device__ int   g_colF[E_];
__device__ int   g_colR[E_];
__device__ float g_pooled[S_ * G_];

// ---------------- helpers ----------------------------------------------------
__device__ __forceinline__ uint32_t smem_u32(const void* p) {
    uint32_t a;
    asm("{ .reg .u64 t; cvta.to.shared.u64 t, %1; cvt.u32.u64 %0, t; }" : "=r"(a) : "l"(p));
    return a;
}

__device__ __forceinline__ void split_h(float v, __half& h, __half& l) {
    h = __float2half(v);
    l = __float2half(v - __half2float(h));
}

__device__ __forceinline__ void cp_async16(uint32_t saddr, const void* gaddr) {
    asm volatile("cp.async.cg.shared.global [%0], [%1], 16;" :: "r"(saddr), "l"(gaddr));
}
#define CP_COMMIT() asm volatile("cp.async.commit_group;" ::: "memory")
#define CP_WAIT2()  asm volatile("cp.async.wait_group 2;" ::: "memory")

// mma.m16n8k16 f16 -> f32 accumulate
__device__ __forceinline__ void mma16816(float* c, const uint32_t* a, uint32_t b0, uint32_t b1) {
    asm volatile("mma.sync.aligned.m16n8k16.row.col.f32.f16.f16.f32 "
        "{%0,%1,%2,%3}, {%4,%5,%6,%7}, {%8,%9}, {%0,%1,%2,%3};"
        : "+f"(c[0]), "+f"(c[1]), "+f"(c[2]), "+f"(c[3])
        : "r"(a[0]), "r"(a[1]), "r"(a[2]), "r"(a[3]), "r"(b0), "r"(b1));
}

// ---------------- prep: transposed split weights ----------------------------
__global__ void wt_kernel(const float* __restrict__ cWl, const float* __restrict__ cWr,
                          const float* __restrict__ rWl, const float* __restrict__ rWr,
                          __half* __restrict__ Wh, __half* __restrict__ Wl_) {
    int idx = blockIdx.x * blockDim.x + threadIdx.x;
    const int total = L_ * 512 * 256;
    if (idx >= total) return;
    int l = idx / (512 * 256);
    int rem = idx - l * (512 * 256);
    int j = rem >> 8;            // output col 0..511
    int k = rem & 255;           // k index
    const float* sp; int col;
    if (j < 128)      { sp = cWl; col = j; }
    else if (j < 256) { sp = rWl; col = j - 128; }
    else if (j < 384) { sp = cWr; col = j - 256; }
    else              { sp = rWr; col = j - 384; }
    float v = sp[((size_t)l * 256 + k) * 128 + col];
    __half h, lo; split_h(v, h, lo);
    Wh[idx] = h; Wl_[idx] = lo;
}

__global__ void pwt_kernel(const float* __restrict__ preW,
                           __half* __restrict__ Wh, __half* __restrict__ Wl_) {
    int idx = blockIdx.x * blockDim.x + threadIdx.x;
    if (idx >= 256 * KPRE) return;
    int j = idx / KPRE;
    int k = idx - j * KPRE;
    float v = (k < INC) ? preW[k * 256 + j] : 0.f;
    __half h, lo; split_h(v, h, lo);
    Wh[idx] = h; Wl_[idx] = lo;
}

// ---------------- degrees + CSR build ----------------------------------------
__global__ void degi_kernel(const int* __restrict__ src, const int* __restrict__ tgt,
                            int* degF, int* degR) {
    int e = blockIdx.x * blockDim.x + threadIdx.x;
    if (e >= E_) return;
    atomicAdd(&degF[tgt[e]], 1);
    atomicAdd(&degR[src[e]], 1);
}

__global__ void inv_kernel(const int* __restrict__ dF, const int* __restrict__ dR,
                           float* invF, float* invR) {
    int n = blockIdx.x * blockDim.x + threadIdx.x;
    if (n >= N_) return;
    invF[n] = 1.f / fmaxf((float)dF[n], 1.f);
    invR[n] = 1.f / fmaxf((float)dR[n], 1.f);
}

// Exclusive scan: one block, 1024 threads, chunked.
__global__ void scan_kernel(const int* __restrict__ deg, int* __restrict__ rowptr, int n) {
    __shared__ int ssum[1024];
    const int t = threadIdx.x;
    const int chunk = (n + 1023) >> 10;
    const int b = t * chunk;
    const int e = min(b + chunk, n);
    int s = 0;
    for (int i = b; i < e; i++) s += deg[i];
    ssum[t] = s;
    __syncthreads();
    for (int o = 1; o < 1024; o <<= 1) {
        int x = (t >= o) ? ssum[t - o] : 0;
        __syncthreads();
        ssum[t] += x;
        __syncthreads();
    }
    int run = ssum[t] - s;   // exclusive prefix of this chunk
    for (int i = b; i < e; i++) { rowptr[i] = run; run += deg[i]; }
    if (t == 1023) rowptr[n] = run;
}

__global__ void fill_kernel(const int* __restrict__ src, const int* __restrict__ tgt,
                            int* curF, int* curR,
                            int* __restrict__ colF, int* __restrict__ colR) {
    int e = blockIdx.x * blockDim.x + threadIdx.x;
    if (e >= E_) return;
    int s = src[e], t = tgt[e];
    int p = atomicAdd(&curF[t], 1);
    colF[p] = s;
    int q = atomicAdd(&curR[s], 1);
    colR[q] = t;
}

// ---------------- feature construction (fp16 hi only) ------------------------
__global__ void feat_kernel(const float* __restrict__ x_feat, const float* __restrict__ dim_feat,
                            const float* __restrict__ layout_feat, const float* __restrict__ tile_feat,
                            const float* __restrict__ opcode_embed,
                            const int* __restrict__ node_opcode, const int* __restrict__ batch,
                            __half* __restrict__ Fh) {
    int idx = blockIdx.x * blockDim.x + threadIdx.x;
    const int total = M_ * KPRE;
    if (idx >= total) return;
    int m = idx / KPRE;
    int c = idx - m * KPRE;
    int s = m & 1;
    int n = m >> 1;
    float v;
    if (c < 53)       v = x_feat[n * 53 + c];
    else if (c < 85)  v = opcode_embed[node_opcode[n] * 32 + (c - 53)];
    else if (c < 223) v = dim_feat[n * 138 + (c - 85)];
    else if (c < 247) v = layout_feat[n * (S_ * 24) + s * 24 + (c - 223)];
    else if (c < 265) v = tile_feat[batch[n] * (S_ * 18) + s * 18 + (c - 247)];
    else              v = 0.f;
    Fh[idx] = __float2half(v);
}

// ---------------- split-weight HMMA GEMM (2-MMA scheme) -----------------------
// Block tile 128x256, 8 warps (2 M x 4 N), warp tile 64x64.
// A: [M,K] row-major fp16. B: [Nout,K] row-major halves hi/lo (= B^T, "col" op).
// acc += Ah*Bh + Ah*Bl.
// mode 0 (pre): relu(acc + preb[col]) -> Xh fp16 [M,256]
// mode 1 (layer): Yout[row*512 + bn + col] = acc
// SMEM per stage: Ah(128x40h=10240B) Bh(256x40h=20480) Bl(20480) = 51200B; 3 stages.
#define STG_B 51200
#define SMEM_TOTAL (3 * STG_B)

__global__ void __launch_bounds__(256, 1)
mma_gemm_k(const __half* __restrict__ Ah,
           const __half* __restrict__ Bh, const __half* __restrict__ Bl,
           int M, int K, int mode, const float* __restrict__ preb,
           float* __restrict__ Yout, __half* __restrict__ Xh) {
    extern __shared__ char smem[];
    const uint32_t sbase = smem_u32(smem);
    const int tid = threadIdx.x, wid = tid >> 5, lane = tid & 31;
    const int bm = blockIdx.x * 128;
    const int bn = blockIdx.y * 256;
    const int warpM = wid & 1, warpN = wid >> 1;
    const int m0 = warpM * 64, n0 = warpN * 64;
    const int g = lane >> 2, tg = lane & 3;
    const int KT = K >> 5;

    auto loadStage = [&](int kt, int s) {
        const uint32_t stB = sbase + s * STG_B;
        const int k0 = kt * 32;
#pragma unroll
        for (int n = 0; n < 10; n++) {
            int i = tid + n * 256;
            const __half* gp; uint32_t sa;
            if (i < 512) {
                int row = i >> 2, c = i & 3;
                int grow = bm + row; if (grow >= M) grow = M - 1;
                gp = Ah + (size_t)grow * K + k0 + c * 8;
                sa = stB + row * 80 + c * 16;
            } else {
                int j = i - 512;
                int which = j >> 10; int u = j & 1023;
                int row = u >> 2, c = u & 3;
                gp = (which ? Bl : Bh) + (size_t)(bn + row) * K + k0 + c * 8;
                sa = stB + 10240 + which * 20480 + row * 80 + c * 16;
            }
            cp_async16(sa, gp);
        }
    };

    float acc[4][8][4];
#pragma unroll
    for (int mt = 0; mt < 4; mt++)
#pragma unroll
        for (int nt = 0; nt < 8; nt++)
#pragma unroll
            for (int q = 0; q < 4; q++) acc[mt][nt][q] = 0.f;

    loadStage(0, 0); CP_COMMIT();
    loadStage(1, 1); CP_COMMIT();
    loadStage(2, 2); CP_COMMIT();

    for (int kt = 0; kt < KT; kt++) {
        const int s = kt % 3;
        CP_WAIT2();
        __syncthreads();
        const char* st = smem + s * STG_B;
#pragma unroll
        for (int k16 = 0; k16 < 2; k16++) {
            uint32_t ah[4][4];
#pragma unroll
            for (int mt = 0; mt < 4; mt++) {
                int row = m0 + mt * 16 + g;
                int off = row * 80 + k16 * 32 + tg * 4;
                const char* pH = st + off;
                ah[mt][0] = *(const uint32_t*)(pH);
                ah[mt][1] = *(const uint32_t*)(pH + 640);
                ah[mt][2] = *(const uint32_t*)(pH + 16);
                ah[mt][3] = *(const uint32_t*)(pH + 656);
            }
#pragma unroll
            for (int nt = 0; nt < 8; nt++) {
                int nrow = n0 + nt * 8 + g;
                int boff = 10240 + nrow * 80 + k16 * 32 + tg * 4;
                uint32_t bh0 = *(const uint32_t*)(st + boff);
                uint32_t bh1 = *(const uint32_t*)(st + boff + 16);
                uint32_t bl0 = *(const uint32_t*)(st + boff + 20480);
                uint32_t bl1 = *(const uint32_t*)(st + boff + 20480 + 16);
#pragma unroll
                for (int mt = 0; mt < 4; mt++) {
                    mma16816(acc[mt][nt], ah[mt], bh0, bh1);
                    mma16816(acc[mt][nt], ah[mt], bl0, bl1);
                }
            }
        }
        __syncthreads();
        if (kt + 3 < KT) loadStage(kt + 3, s);
        CP_COMMIT();
    }

    // Epilogue. c0,c1: (row=g, col=tg*2+{0,1}); c2,c3: row=g+8.
#pragma unroll
    for (int mt = 0; mt < 4; mt++) {
#pragma unroll
        for (int nt = 0; nt < 8; nt++) {
            int row = bm + m0 + mt * 16 + g;
            int colL = n0 + nt * 8 + tg * 2;       // 0..255 within block
            int col = bn + colL;
            float* c = acc[mt][nt];
            if (mode == 1) {
                if (row < M) {
                    float2 v = make_float2(c[0], c[1]);
                    *(float2*)(Yout + (size_t)row * 512 + col) = v;
                }
                if (row + 8 < M) {
                    float2 v = make_float2(c[2], c[3]);
                    *(float2*)(Yout + (size_t)(row + 8) * 512 + col) = v;
                }
            } else {
                float b0 = preb[col], b1 = preb[col + 1];
                if (row < M) {
                    __half2 hh;
                    hh.x = __float2half(fmaxf(c[0] + b0, 0.f));
                    hh.y = __float2half(fmaxf(c[1] + b1, 0.f));
                    *(__half2*)(Xh + (size_t)row * 256 + col) = hh;
                }
                if (row + 8 < M) {
                    __half2 hh;
                    hh.x = __float2half(fmaxf(c[2] + b0, 0.f));
                    hh.y = __float2half(fmaxf(c[3] + b1, 0.f));
                    *(__half2*)(Xh + (size_t)(row + 8) * 256 + col) = hh;
                }
            }
        }
    }
}

// ---------------- CSR gather + combine + relu + fp16 + pool -------------------
// One warp per m-row. Y row = 128 float4: [0:32)=fwd msg, [32:64)=rev msg,
// [64:96)=conv self, [96:128)=rev self. Lane handles 4 fwd ch + 4 rev ch.
__global__ void gather_combine(const float4* __restrict__ Y4,
                               const int* __restrict__ rowF, const int* __restrict__ colF,
                               const int* __restrict__ rowR, const int* __restrict__ colR,
                               const float* __restrict__ invF, const float* __restrict__ invR,
                               const float* __restrict__ cb, const float* __restrict__ rb,
                               const float* __restrict__ headW, const int* __restrict__ batch,
                               float* __restrict__ pooled, int layer,
                               __half* __restrict__ Xh) {
    int warp = (blockIdx.x * blockDim.x + threadIdx.x) >> 5;
    int lane = threadIdx.x & 31;
    if (warp >= M_) return;
    const int m = warp;
    const int n = m >> 1;
    const int smp = m & 1;

    float4 aF = make_float4(0.f, 0.f, 0.f, 0.f);
    {
        int beg = __ldg(rowF + n), end = __ldg(rowF + n + 1);
        for (int j = beg; j < end; j++) {
            int sn = __ldg(colF + j);
            float4 v = __ldg(Y4 + (size_t)(2 * sn + smp) * 128 + lane);
            aF.x += v.x; aF.y += v.y; aF.z += v.z; aF.w += v.w;
        }
    }
    float4 aR = make_float4(0.f, 0.f, 0.f, 0.f);
    {
        int beg = __ldg(rowR + n), end = __ldg(rowR + n + 1);
        for (int j = beg; j < end; j++) {
            int tn = __ldg(colR + j);
            float4 v = __ldg(Y4 + (size_t)(2 * tn + smp) * 128 + 32 + lane);
            aR.x += v.x; aR.y += v.y; aR.z += v.z; aR.w += v.w;
        }
    }

    const float iF = invF[n];
    const float iR = invR[n];
    const float4* yRow = Y4 + (size_t)m * 128;
    float4 sF = __ldg(yRow + 64 + lane);
    float4 sR = __ldg(yRow + 96 + lane);
    float4 bF = *(const float4*)(cb + lane * 4);
    float4 bR = *(const float4*)(rb + lane * 4);

    float f0 = fmaxf(sF.x + aF.x * iF + bF.x, 0.f);
    float f1 = fmaxf(sF.y + aF.y * iF + bF.y, 0.f);
    float f2 = fmaxf(sF.z + aF.z * iF + bF.z, 0.f);
    float f3 = fmaxf(sF.w + aF.w * iF + bF.w, 0.f);
    float r0 = fmaxf(sR.x + aR.x * iR + bR.x, 0.f);
    float r1 = fmaxf(sR.y + aR.y * iR + bR.y, 0.f);
    float r2 = fmaxf(sR.z + aR.z * iR + bR.z, 0.f);
    float r3 = fmaxf(sR.w + aR.w * iR + bR.w, 0.f);

    if (layer < L_ - 1) {
        __half2 a, b;
        a.x = __float2half(f0); a.y = __float2half(f1);
        b.x = __float2half(f2); b.y = __float2half(f3);
        *(__half2*)(Xh + (size_t)m * 256 + lane * 4)     = a;
        *(__half2*)(Xh + (size_t)m * 256 + lane * 4 + 2) = b;
        a.x = __float2half(r0); a.y = __float2half(r1);
        b.x = __float2half(r2); b.y = __float2half(r3);
        *(__half2*)(Xh + (size_t)m * 256 + 128 + lane * 4)     = a;
        *(__half2*)(Xh + (size_t)m * 256 + 128 + lane * 4 + 2) = b;
    }

    if (layer >= L_ - 2) {
        const int hoff = (layer - (L_ - 2)) * 256;
        float4 wF = __ldg((const float4*)(headW + hoff) + lane);
        float4 wR = __ldg((const float4*)(headW + hoff + 128) + lane);
        float dot = f0 * wF.x + f1 * wF.y + f2 * wF.z + f3 * wF.w
                  + r0 * wR.x + r1 * wR.y + r2 * wR.z + r3 * wR.w;
#pragma unroll
        for (int o = 16; o; o >>= 1) dot += __shfl_down_sync(0xffffffffu, dot, o);
        if (lane == 0) atomicAdd(&pooled[smp * G_ + batch[n]], dot);
    }
}

// ---------------- final ------------------------------------------------------
__global__ void final_kernel(const float* __restrict__ pooled, const float* __restrict__ headb,
                             float* __restrict__ out) {
    int i = threadIdx.x;
    if (i < S_ * G_) {
        int g = i >> 1;
        int s = i & 1;
        out[i] = pooled[s * G_ + g] + headb[0];
    }
}

// ---------------- launch -----------------------------------------------------
extern "C" void kernel_launch(void* const* d_in, const int* in_sizes, int n_in,
                              void* d_out, int out_size) {
    const float* x_feat       = (const float*)d_in[0];
    const float* dim_feat     = (const float*)d_in[1];
    const float* layout_feat  = (const float*)d_in[2];
    const float* tile_feat    = (const float*)d_in[3];
    const float* opcode_embed = (const float*)d_in[4];
    const float* preW         = (const float*)d_in[5];
    const float* preb         = (const float*)d_in[6];
    const float* convWl       = (const float*)d_in[7];
    const float* convWr       = (const float*)d_in[8];
    const float* convb        = (const float*)d_in[9];
    const float* revWl        = (const float*)d_in[10];
    const float* revWr        = (const float*)d_in[11];
    const float* revb         = (const float*)d_in[12];
    const float* headW        = (const float*)d_in[13];
    const float* headb        = (const float*)d_in[14];
    const int*   node_opcode  = (const int*)d_in[15];
    const int*   batch        = (const int*)d_in[16];
    const int*   edge_index   = (const int*)d_in[17];
    const int* src = edge_index;
    const int* tgt = edge_index + E_;

    float *Y, *invF, *invR, *pooled;
    int *degFi, *degRi, *rowF, *rowR, *curF, *curR, *colF, *colR;
    __half *Xh0, *Xh1, *Fh, *Wth, *Wtl, *PWh, *PWl;
    cudaGetSymbolAddress((void**)&Y,    g_Y);
    cudaGetSymbolAddress((void**)&Xh0,  g_Xh0);
    cudaGetSymbolAddress((void**)&Xh1,  g_Xh1);
    cudaGetSymbolAddress((void**)&Fh,   g_Fh);
    cudaGetSymbolAddress((void**)&Wth,  g_Wth);
    cudaGetSymbolAddress((void**)&Wtl,  g_Wtl);
    cudaGetSymbolAddress((void**)&PWh,  g_PWh);
    cudaGetSymbolAddress((void**)&PWl,  g_PWl);
    cudaGetSymbolAddress((void**)&invF, g_invF);
    cudaGetSymbolAddress((void**)&invR, g_invR);
    cudaGetSymbolAddress((void**)&degFi, g_degFi);
    cudaGetSymbolAddress((void**)&degRi, g_degRi);
    cudaGetSymbolAddress((void**)&rowF, g_rowF);
    cudaGetSymbolAddress((void**)&rowR, g_rowR);
    cudaGetSymbolAddress((void**)&curF, g_curF);
    cudaGetSymbolAddress((void**)&curR, g_curR);
    cudaGetSymbolAddress((void**)&colF, g_colF);
    cudaGetSymbolAddress((void**)&colR, g_colR);
    cudaGetSymbolAddress((void**)&pooled, g_pooled);

    cudaFuncSetAttribute(mma_gemm_k, cudaFuncAttributeMaxDynamicSharedMemorySize, SMEM_TOTAL);

    // Launch order puts layer-0 GEMM at launch index 5 so ncu (-s 5 -c 1)
    // profiles it (memsets count as launches).
    wt_kernel<<<(L_ * 512 * 256 + 255) / 256, 256>>>(convWl, convWr, revWl, revWr, Wth, Wtl);   // 0
    pwt_kernel<<<(256 * KPRE + 255) / 256, 256>>>(preW, PWh, PWl);                              // 1
    feat_kernel<<<(int)(((size_t)M_ * KPRE + 255) / 256), 256>>>(                               // 2
        x_feat, dim_feat, layout_feat, tile_feat, opcode_embed, node_opcode, batch, Fh);
    {
        dim3 gr((M_ + 127) / 128, 1);                                                           // 3
        mma_gemm_k<<<gr, 256, SMEM_TOTAL>>>(Fh, PWh, PWl, M_, KPRE, 0, preb, nullptr, Xh0);
    }
    cudaMemsetAsync(degFi, 0, (size_t)N_ * 4);                                                  // 4
    {
        dim3 gr((M_ + 127) / 128, 2);                                                           // 5 <- profiled
        mma_gemm_k<<<gr, 256, SMEM_TOTAL>>>(Xh0, Wth, Wtl, M_, 256, 1, nullptr, Y, nullptr);
    }
    // CSR prep (needed before gather of layer 0)
    cudaMemsetAsync(degRi, 0, (size_t)N_ * 4);
    cudaMemsetAsync(pooled, 0, (size_t)S_ * G_ * 4);
    degi_kernel<<<(E_ + 255) / 256, 256>>>(src, tgt, degFi, degRi);
    inv_kernel<<<(N_ + 255) / 256, 256>>>(degFi, degRi, invF, invR);
    scan_kernel<<<1, 1024>>>(degFi, rowF, N_);
    scan_kernel<<<1, 1024>>>(degRi, rowR, N_);
    cudaMemcpyAsync(curF, rowF, (size_t)N_ * 4, cudaMemcpyDeviceToDevice);
    cudaMemcpyAsync(curR, rowR, (size_t)N_ * 4, cudaMemcpyDeviceToDevice);
    fill_kernel<<<(E_ + 255) / 256, 256>>>(src, tgt, curF, curR, colF, colR);

    gather_combine<<<(M_ * 32 + 255) / 256, 256>>>(
        (const float4*)Y, rowF, colF, rowR, colR, invF, invR,
        convb, revb, headW, batch, pooled, 0, Xh1);

    __half *curH = Xh1, *nxtH = Xh0;
    for (int l = 1; l < L_; l++) {
        dim3 gr((M_ + 127) / 128, 2);
        mma_gemm_k<<<gr, 256, SMEM_TOTAL>>>(curH, Wth + (size_t)l * 512 * 256,
                                            Wtl + (size_t)l * 512 * 256,
                                            M_, 256, 1, nullptr, Y, nullptr);
        gather_combine<<<(M_ * 32 + 255) / 256, 256>>>(
            (const float4*)Y, rowF, colF, rowR, colR, invF, invR,
            convb + l * 128, revb + l * 128, headW, batch, pooled, l, nxtH);
        __half* t = curH; curH = nxtH; nxtH = t;
    }

    final_kernel<<<1, 32>>>(pooled, headb, (float*)d_out);
}

// round 17
// speedup vs baseline: 3.5656x; 1.3609x over previous
#include <cuda_runtime.h>
#include <cuda_fp16.h>
#include <cstdint>

// Problem constants
#define N_   100000
#define S_   2
#define G_   8
#define E_   400000
#define L_   4
#define INC  265
#define KPRE 288          // padded pre-layer K (9 chunks of 32)
#define M_   (N_ * S_)    // 200000 rows

// ---------------- scratch (device globals; no allocation allowed) ----------
__device__ __half  g_Y  [(size_t)M_ * 512];     // layer GEMM out (fp16)
__device__ __half  g_Xh0[(size_t)M_ * 256];
__device__ __half  g_Xh1[(size_t)M_ * 256];
__device__ __half  g_Fh [(size_t)M_ * KPRE];
__device__ __half  g_Wth[(size_t)L_ * 512 * 256];  // W^T fp16: [l][out col j][k]
__device__ __half  g_PWh[(size_t)256 * KPRE];      // preW^T fp16 [256][288]
__device__ float g_invF[N_];
__device__ float g_invR[N_];
__device__ int   g_degFi[N_];
__device__ int   g_degRi[N_];
__device__ int   g_rowF[N_ + 1];
__device__ int   g_rowR[N_ + 1];
__device__ int   g_curF[N_];
__device__ int   g_curR[N_];
__device__ int   g_colF[E_];
__device__ int   g_colR[E_];
__device__ float g_pooled[S_ * G_];

// ---------------- helpers ----------------------------------------------------
__device__ __forceinline__ uint32_t smem_u32(const void* p) {
    uint32_t a;
    asm("{ .reg .u64 t; cvta.to.shared.u64 t, %1; cvt.u32.u64 %0, t; }" : "=r"(a) : "l"(p));
    return a;
}

__device__ __forceinline__ void cp_async16(uint32_t saddr, const void* gaddr) {
    asm volatile("cp.async.cg.shared.global [%0], [%1], 16;" :: "r"(saddr), "l"(gaddr));
}
#define CP_COMMIT() asm volatile("cp.async.commit_group;" ::: "memory")
#define CP_WAIT2()  asm volatile("cp.async.wait_group 2;" ::: "memory")

// mma.m16n8k16 f16 -> f32 accumulate
__device__ __forceinline__ void mma16816(float* c, const uint32_t* a, uint32_t b0, uint32_t b1) {
    asm volatile("mma.sync.aligned.m16n8k16.row.col.f32.f16.f16.f32 "
        "{%0,%1,%2,%3}, {%4,%5,%6,%7}, {%8,%9}, {%0,%1,%2,%3};"
        : "+f"(c[0]), "+f"(c[1]), "+f"(c[2]), "+f"(c[3])
        : "r"(a[0]), "r"(a[1]), "r"(a[2]), "r"(a[3]), "r"(b0), "r"(b1));
}

// ---------------- prep: transposed fp16 weights ------------------------------
__global__ void wt_kernel(const float* __restrict__ cWl, const float* __restrict__ cWr,
                          const float* __restrict__ rWl, const float* __restrict__ rWr,
                          __half* __restrict__ Wh) {
    int idx = blockIdx.x * blockDim.x + threadIdx.x;
    const int total = L_ * 512 * 256;
    if (idx >= total) return;
    int l = idx / (512 * 256);
    int rem = idx - l * (512 * 256);
    int j = rem >> 8;            // output col 0..511
    int k = rem & 255;           // k index
    const float* sp; int col;
    if (j < 128)      { sp = cWl; col = j; }
    else if (j < 256) { sp = rWl; col = j - 128; }
    else if (j < 384) { sp = cWr; col = j - 256; }
    else              { sp = rWr; col = j - 384; }
    Wh[idx] = __float2half(sp[((size_t)l * 256 + k) * 128 + col]);
}

__global__ void pwt_kernel(const float* __restrict__ preW, __half* __restrict__ Wh) {
    int idx = blockIdx.x * blockDim.x + threadIdx.x;
    if (idx >= 256 * KPRE) return;
    int j = idx / KPRE;
    int k = idx - j * KPRE;
    Wh[idx] = __float2half((k < INC) ? preW[k * 256 + j] : 0.f);
}

// ---------------- degrees + CSR build ----------------------------------------
__global__ void degi_kernel(const int* __restrict__ src, const int* __restrict__ tgt,
                            int* degF, int* degR) {
    int e = blockIdx.x * blockDim.x + threadIdx.x;
    if (e >= E_) return;
    atomicAdd(&degF[tgt[e]], 1);
    atomicAdd(&degR[src[e]], 1);
}

__global__ void inv_kernel(const int* __restrict__ dF, const int* __restrict__ dR,
                           float* invF, float* invR) {
    int n = blockIdx.x * blockDim.x + threadIdx.x;
    if (n >= N_) return;
    invF[n] = 1.f / fmaxf((float)dF[n], 1.f);
    invR[n] = 1.f / fmaxf((float)dR[n], 1.f);
}

// Exclusive scan: one block, 1024 threads, chunked.
__global__ void scan_kernel(const int* __restrict__ deg, int* __restrict__ rowptr, int n) {
    __shared__ int ssum[1024];
    const int t = threadIdx.x;
    const int chunk = (n + 1023) >> 10;
    const int b = t * chunk;
    const int e = min(b + chunk, n);
    int s = 0;
    for (int i = b; i < e; i++) s += deg[i];
    ssum[t] = s;
    __syncthreads();
    for (int o = 1; o < 1024; o <<= 1) {
        int x = (t >= o) ? ssum[t - o] : 0;
        __syncthreads();
        ssum[t] += x;
        __syncthreads();
    }
    int run = ssum[t] - s;   // exclusive prefix of this chunk
    for (int i = b; i < e; i++) { rowptr[i] = run; run += deg[i]; }
    if (t == 1023) rowptr[n] = run;
}

__global__ void fill_kernel(const int* __restrict__ src, const int* __restrict__ tgt,
                            int* curF, int* curR,
                            int* __restrict__ colF, int* __restrict__ colR) {
    int e = blockIdx.x * blockDim.x + threadIdx.x;
    if (e >= E_) return;
    int s = src[e], t = tgt[e];
    int p = atomicAdd(&curF[t], 1);
    colF[p] = s;
    int q = atomicAdd(&curR[s], 1);
    colR[q] = t;
}

// ---------------- feature construction (fp16) ---------------------------------
__global__ void feat_kernel(const float* __restrict__ x_feat, const float* __restrict__ dim_feat,
                            const float* __restrict__ layout_feat, const float* __restrict__ tile_feat,
                            const float* __restrict__ opcode_embed,
                            const int* __restrict__ node_opcode, const int* __restrict__ batch,
                            __half* __restrict__ Fh) {
    int idx = blockIdx.x * blockDim.x + threadIdx.x;
    const int total = M_ * KPRE;
    if (idx >= total) return;
    int m = idx / KPRE;
    int c = idx - m * KPRE;
    int s = m & 1;
    int n = m >> 1;
    float v;
    if (c < 53)       v = x_feat[n * 53 + c];
    else if (c < 85)  v = opcode_embed[node_opcode[n] * 32 + (c - 53)];
    else if (c < 223) v = dim_feat[n * 138 + (c - 85)];
    else if (c < 247) v = layout_feat[n * (S_ * 24) + s * 24 + (c - 223)];
    else if (c < 265) v = tile_feat[batch[n] * (S_ * 18) + s * 18 + (c - 247)];
    else              v = 0.f;
    Fh[idx] = __float2half(v);
}

// ---------------- fp16 HMMA GEMM ---------------------------------------------
// Block tile 128x256, 8 warps (2 M x 4 N), warp tile 64x64, single MMA.
// A: [M,K] row-major fp16. B: [Nout,K] row-major fp16 (= B^T, "col" operand).
// mode 0 (pre): relu(acc + preb[col]) -> Xh fp16 [M,256]
// mode 1 (layer): Yout[row*512 + bn + col] = fp16(acc)
// SMEM per stage: A(128x40h=10240B) B(256x40h=20480B) = 30720B; 3 stages.
#define STG_B 30720
#define SMEM_TOTAL (3 * STG_B)

__global__ void __launch_bounds__(256, 1)
mma_gemm_k(const __half* __restrict__ Ah, const __half* __restrict__ Bh,
           int M, int K, int mode, const float* __restrict__ preb,
           __half* __restrict__ Yout, __half* __restrict__ Xh) {
    extern __shared__ char smem[];
    const uint32_t sbase = smem_u32(smem);
    const int tid = threadIdx.x, wid = tid >> 5, lane = tid & 31;
    const int bm = blockIdx.x * 128;
    const int bn = blockIdx.y * 256;
    const int warpM = wid & 1, warpN = wid >> 1;
    const int m0 = warpM * 64, n0 = warpN * 64;
    const int g = lane >> 2, tg = lane & 3;
    const int KT = K >> 5;

    auto loadStage = [&](int kt, int s) {
        const uint32_t stB = sbase + s * STG_B;
        const int k0 = kt * 32;
#pragma unroll
        for (int n = 0; n < 6; n++) {
            int i = tid + n * 256;
            const __half* gp; uint32_t sa;
            if (i < 512) {
                int row = i >> 2, c = i & 3;
                int grow = bm + row; if (grow >= M) grow = M - 1;
                gp = Ah + (size_t)grow * K + k0 + c * 8;
                sa = stB + row * 80 + c * 16;
            } else {
                int u = i - 512;
                int row = u >> 2, c = u & 3;
                gp = Bh + (size_t)(bn + row) * K + k0 + c * 8;
                sa = stB + 10240 + row * 80 + c * 16;
            }
            cp_async16(sa, gp);
        }
    };

    float acc[4][8][4];
#pragma unroll
    for (int mt = 0; mt < 4; mt++)
#pragma unroll
        for (int nt = 0; nt < 8; nt++)
#pragma unroll
            for (int q = 0; q < 4; q++) acc[mt][nt][q] = 0.f;

    loadStage(0, 0); CP_COMMIT();
    loadStage(1, 1); CP_COMMIT();
    loadStage(2, 2); CP_COMMIT();

    for (int kt = 0; kt < KT; kt++) {
        const int s = kt % 3;
        CP_WAIT2();
        __syncthreads();
        const char* st = smem + s * STG_B;
#pragma unroll
        for (int k16 = 0; k16 < 2; k16++) {
            uint32_t ah[4][4];
#pragma unroll
            for (int mt = 0; mt < 4; mt++) {
                int row = m0 + mt * 16 + g;
                int off = row * 80 + k16 * 32 + tg * 4;
                const char* pH = st + off;
                ah[mt][0] = *(const uint32_t*)(pH);
                ah[mt][1] = *(const uint32_t*)(pH + 640);
                ah[mt][2] = *(const uint32_t*)(pH + 16);
                ah[mt][3] = *(const uint32_t*)(pH + 656);
            }
#pragma unroll
            for (int nt = 0; nt < 8; nt++) {
                int nrow = n0 + nt * 8 + g;
                int boff = 10240 + nrow * 80 + k16 * 32 + tg * 4;
                uint32_t bh0 = *(const uint32_t*)(st + boff);
                uint32_t bh1 = *(const uint32_t*)(st + boff + 16);
#pragma unroll
                for (int mt = 0; mt < 4; mt++) {
                    mma16816(acc[mt][nt], ah[mt], bh0, bh1);
                }
            }
        }
        __syncthreads();
        if (kt + 3 < KT) loadStage(kt + 3, s);
        CP_COMMIT();
    }

    // Epilogue. c0,c1: (row=g, col=tg*2+{0,1}); c2,c3: row=g+8.
#pragma unroll
    for (int mt = 0; mt < 4; mt++) {
#pragma unroll
        for (int nt = 0; nt < 8; nt++) {
            int row = bm + m0 + mt * 16 + g;
            int colL = n0 + nt * 8 + tg * 2;       // 0..255 within block
            int col = bn + colL;
            float* c = acc[mt][nt];
            if (mode == 1) {
                if (row < M) {
                    __half2 v; v.x = __float2half(c[0]); v.y = __float2half(c[1]);
                    *(__half2*)(Yout + (size_t)row * 512 + col) = v;
                }
                if (row + 8 < M) {
                    __half2 v; v.x = __float2half(c[2]); v.y = __float2half(c[3]);
                    *(__half2*)(Yout + (size_t)(row + 8) * 512 + col) = v;
                }
            } else {
                float b0 = preb[col], b1 = preb[col + 1];
                if (row < M) {
                    __half2 hh;
                    hh.x = __float2half(fmaxf(c[0] + b0, 0.f));
                    hh.y = __float2half(fmaxf(c[1] + b1, 0.f));
                    *(__half2*)(Xh + (size_t)row * 256 + col) = hh;
                }
                if (row + 8 < M) {
                    __half2 hh;
                    hh.x = __float2half(fmaxf(c[2] + b0, 0.f));
                    hh.y = __float2half(fmaxf(c[3] + b1, 0.f));
                    *(__half2*)(Xh + (size_t)(row + 8) * 256 + col) = hh;
                }
            }
        }
    }
}

// ---------------- CSR gather + combine + relu + fp16 + pool -------------------
// One warp per m-row. Y row = 512 halves: [0:128)=fwd msg, [128:256)=rev msg,
// [256:384)=conv self, [384:512)=rev self. Lane handles 4 ch of each part.
__device__ __forceinline__ void acc4h(float4& a, uint2 v) {
    float2 p0 = __half22float2(*(__half2*)&v.x);
    float2 p1 = __half22float2(*(__half2*)&v.y);
    a.x += p0.x; a.y += p0.y; a.z += p1.x; a.w += p1.y;
}

__global__ void gather_combine(const __half* __restrict__ Yh,
                               const int* __restrict__ rowF, const int* __restrict__ colF,
                               const int* __restrict__ rowR, const int* __restrict__ colR,
                               const float* __restrict__ invF, const float* __restrict__ invR,
                               const float* __restrict__ cb, const float* __restrict__ rb,
                               const float* __restrict__ headW, const int* __restrict__ batch,
                               float* __restrict__ pooled, int layer,
                               __half* __restrict__ Xh) {
    int warp = (blockIdx.x * blockDim.x + threadIdx.x) >> 5;
    int lane = threadIdx.x & 31;
    if (warp >= M_) return;
    const int m = warp;
    const int n = m >> 1;
    const int smp = m & 1;

    float4 aF = make_float4(0.f, 0.f, 0.f, 0.f);
    {
        int beg = __ldg(rowF + n), end = __ldg(rowF + n + 1);
        for (int j = beg; j < end; j++) {
            int sn = __ldg(colF + j);
            uint2 v = __ldg((const uint2*)(Yh + (size_t)(2 * sn + smp) * 512) + lane);
            acc4h(aF, v);
        }
    }
    float4 aR = make_float4(0.f, 0.f, 0.f, 0.f);
    {
        int beg = __ldg(rowR + n), end = __ldg(rowR + n + 1);
        for (int j = beg; j < end; j++) {
            int tn = __ldg(colR + j);
            uint2 v = __ldg((const uint2*)(Yh + (size_t)(2 * tn + smp) * 512 + 128) + lane);
            acc4h(aR, v);
        }
    }

    const float iF = invF[n];
    const float iR = invR[n];
    const __half* yRow = Yh + (size_t)m * 512;
    float4 sF = make_float4(0.f, 0.f, 0.f, 0.f);
    float4 sR = make_float4(0.f, 0.f, 0.f, 0.f);
    acc4h(sF, __ldg((const uint2*)(yRow + 256) + lane));
    acc4h(sR, __ldg((const uint2*)(yRow + 384) + lane));
    float4 bF = *(const float4*)(cb + lane * 4);
    float4 bR = *(const float4*)(rb + lane * 4);

    float f0 = fmaxf(sF.x + aF.x * iF + bF.x, 0.f);
    float f1 = fmaxf(sF.y + aF.y * iF + bF.y, 0.f);
    float f2 = fmaxf(sF.z + aF.z * iF + bF.z, 0.f);
    float f3 = fmaxf(sF.w + aF.w * iF + bF.w, 0.f);
    float r0 = fmaxf(sR.x + aR.x * iR + bR.x, 0.f);
    float r1 = fmaxf(sR.y + aR.y * iR + bR.y, 0.f);
    float r2 = fmaxf(sR.z + aR.z * iR + bR.z, 0.f);
    float r3 = fmaxf(sR.w + aR.w * iR + bR.w, 0.f);

    if (layer < L_ - 1) {
        __half2 a, b;
        a.x = __float2half(f0); a.y = __float2half(f1);
        b.x = __float2half(f2); b.y = __float2half(f3);
        *(__half2*)(Xh + (size_t)m * 256 + lane * 4)     = a;
        *(__half2*)(Xh + (size_t)m * 256 + lane * 4 + 2) = b;
        a.x = __float2half(r0); a.y = __float2half(r1);
        b.x = __float2half(r2); b.y = __float2half(r3);
        *(__half2*)(Xh + (size_t)m * 256 + 128 + lane * 4)     = a;
        *(__half2*)(Xh + (size_t)m * 256 + 128 + lane * 4 + 2) = b;
    }

    if (layer >= L_ - 2) {
        const int hoff = (layer - (L_ - 2)) * 256;
        float4 wF = __ldg((const float4*)(headW + hoff) + lane);
        float4 wR = __ldg((const float4*)(headW + hoff + 128) + lane);
        float dot = f0 * wF.x + f1 * wF.y + f2 * wF.z + f3 * wF.w
                  + r0 * wR.x + r1 * wR.y + r2 * wR.z + r3 * wR.w;
#pragma unroll
        for (int o = 16; o; o >>= 1) dot += __shfl_down_sync(0xffffffffu, dot, o);
        if (lane == 0) atomicAdd(&pooled[smp * G_ + batch[n]], dot);
    }
}

// ---------------- final ------------------------------------------------------
__global__ void final_kernel(const float* __restrict__ pooled, const float* __restrict__ headb,
                             float* __restrict__ out) {
    int i = threadIdx.x;
    if (i < S_ * G_) {
        int g = i >> 1;
        int s = i & 1;
        out[i] = pooled[s * G_ + g] + headb[0];
    }
}

// ---------------- launch -----------------------------------------------------
extern "C" void kernel_launch(void* const* d_in, const int* in_sizes, int n_in,
                              void* d_out, int out_size) {
    const float* x_feat       = (const float*)d_in[0];
    const float* dim_feat     = (const float*)d_in[1];
    const float* layout_feat  = (const float*)d_in[2];
    const float* tile_feat    = (const float*)d_in[3];
    const float* opcode_embed = (const float*)d_in[4];
    const float* preW         = (const float*)d_in[5];
    const float* preb         = (const float*)d_in[6];
    const float* convWl       = (const float*)d_in[7];
    const float* convWr       = (const float*)d_in[8];
    const float* convb        = (const float*)d_in[9];
    const float* revWl        = (const float*)d_in[10];
    const float* revWr        = (const float*)d_in[11];
    const float* revb         = (const float*)d_in[12];
    const float* headW        = (const float*)d_in[13];
    const float* headb        = (const float*)d_in[14];
    const int*   node_opcode  = (const int*)d_in[15];
    const int*   batch        = (const int*)d_in[16];
    const int*   edge_index   = (const int*)d_in[17];
    const int* src = edge_index;
    const int* tgt = edge_index + E_;

    float *invF, *invR, *pooled;
    int *degFi, *degRi, *rowF, *rowR, *curF, *curR, *colF, *colR;
    __half *Y, *Xh0, *Xh1, *Fh, *Wth, *PWh;
    cudaGetSymbolAddress((void**)&Y,    g_Y);
    cudaGetSymbolAddress((void**)&Xh0,  g_Xh0);
    cudaGetSymbolAddress((void**)&Xh1,  g_Xh1);
    cudaGetSymbolAddress((void**)&Fh,   g_Fh);
    cudaGetSymbolAddress((void**)&Wth,  g_Wth);
    cudaGetSymbolAddress((void**)&PWh,  g_PWh);
    cudaGetSymbolAddress((void**)&invF, g_invF);
    cudaGetSymbolAddress((void**)&invR, g_invR);
    cudaGetSymbolAddress((void**)&degFi, g_degFi);
    cudaGetSymbolAddress((void**)&degRi, g_degRi);
    cudaGetSymbolAddress((void**)&rowF, g_rowF);
    cudaGetSymbolAddress((void**)&rowR, g_rowR);
    cudaGetSymbolAddress((void**)&curF, g_curF);
    cudaGetSymbolAddress((void**)&curR, g_curR);
    cudaGetSymbolAddress((void**)&colF, g_colF);
    cudaGetSymbolAddress((void**)&colR, g_colR);
    cudaGetSymbolAddress((void**)&pooled, g_pooled);

    cudaFuncSetAttribute(mma_gemm_k, cudaFuncAttributeMaxDynamicSharedMemorySize, SMEM_TOTAL);

    // Launch order puts layer-0 GEMM at launch index 5 so ncu (-s 5 -c 1)
    // profiles it (memsets count as launches).
    wt_kernel<<<(L_ * 512 * 256 + 255) / 256, 256>>>(convWl, convWr, revWl, revWr, Wth);        // 0
    pwt_kernel<<<(256 * KPRE + 255) / 256, 256>>>(preW, PWh);                                   // 1
    feat_kernel<<<(int)(((size_t)M_ * KPRE + 255) / 256), 256>>>(                               // 2
        x_feat, dim_feat, layout_feat, tile_feat, opcode_embed, node_opcode, batch, Fh);
    {
        dim3 gr((M_ + 127) / 128, 1);                                                           // 3
        mma_gemm_k<<<gr, 256, SMEM_TOTAL>>>(Fh, PWh, M_, KPRE, 0, preb, nullptr, Xh0);
    }
    cudaMemsetAsync(degFi, 0, (size_t)N_ * 4);                                                  // 4
    {
        dim3 gr((M_ + 127) / 128, 2);                                                           // 5 <- profiled
        mma_gemm_k<<<gr, 256, SMEM_TOTAL>>>(Xh0, Wth, M_, 256, 1, nullptr, Y, nullptr);
    }
    // CSR prep (needed before gather of layer 0)
    cudaMemsetAsync(degRi, 0, (size_t)N_ * 4);
    cudaMemsetAsync(pooled, 0, (size_t)S_ * G_ * 4);
    degi_kernel<<<(E_ + 255) / 256, 256>>>(src, tgt, degFi, degRi);
    inv_kernel<<<(N_ + 255) / 256, 256>>>(degFi, degRi, invF, invR);
    scan_kernel<<<1, 1024>>>(degFi, rowF, N_);
    scan_kernel<<<1, 1024>>>(degRi, rowR, N_);
    cudaMemcpyAsync(curF, rowF, (size_t)N_ * 4, cudaMemcpyDeviceToDevice);
    cudaMemcpyAsync(curR, rowR, (size_t)N_ * 4, cudaMemcpyDeviceToDevice);
    fill_kernel<<<(E_ + 255) / 256, 256>>>(src, tgt, curF, curR, colF, colR);

    gather_combine<<<(M_ * 32 + 255) / 256, 256>>>(
        Y, rowF, colF, rowR, colR, invF, invR,
        convb, revb, headW, batch, pooled, 0, Xh1);

    __half *curH = Xh1, *nxtH = Xh0;
    for (int l = 1; l < L_; l++) {
        dim3 gr((M_ + 127) / 128, 2);
        mma_gemm_k<<<gr, 256, SMEM_TOTAL>>>(curH, Wth + (size_t)l * 512 * 256,
                                            M_, 256, 1, nullptr, Y, nullptr);
        gather_combine<<<(M_ * 32 + 255) / 256, 256>>>(
            Y, rowF, colF, rowR, colR, invF, invR,
            convb + l * 128, revb + l * 128, headW, batch, pooled, l, nxtH);
        __half* t = curH; curH = nxtH; nxtH = t;
    }

    final_kernel<<<1, 32>>>(pooled, headb, (float*)d_out);
}